// round 7
// baseline (speedup 1.0000x reference)
#include <cuda_runtime.h>
#include <cuda_fp16.h>
#include <math.h>
#include <stdint.h>

// ---------------------------------------------------------------------------
// WaveletSwinTransformerBlock — fp16 mma GEMMs (ldmatrix + 3-stage pipe)
// ---------------------------------------------------------------------------

#define B_     8
#define H_     128
#define W_     128
#define HW_    (H_*W_)           // 16384
#define P_TOT  (B_*HW_)          // 131072
#define CDIM   256
#define NHEAD  8
#define HD     32
#define HID    1024

// ------------------------- scratch buffers (static) ------------------------
__device__ __half g_inx[(size_t)P_TOT*128];
__device__ __half g_iny[(size_t)P_TOT*64];
__device__ __half g_inz[(size_t)P_TOT*64];
__device__ __half g_x    [(size_t)P_TOT*CDIM];
__device__ __half g_y    [(size_t)P_TOT*CDIM];
__device__ __half g_xn   [(size_t)P_TOT*CDIM];
__device__ __half g_yn   [(size_t)P_TOT*CDIM];
__device__ float  g_short[(size_t)P_TOT*CDIM];
__device__ __half g_q    [(size_t)P_TOT*CDIM];
__device__ __half g_kv   [(size_t)P_TOT*512];
__device__ __half g_ao   [(size_t)P_TOT*CDIM];
__device__ __half g_po   [(size_t)P_TOT*CDIM];
__device__ float  g_zt   [(size_t)P_TOT*CDIM];
__device__ __half g_ln2  [(size_t)P_TOT*CDIM];
__device__ __half g_h    [(size_t)P_TOT*HID];
__device__ float  g_zt2  [(size_t)P_TOT*CDIM];

// fp16 weights, concatenated
#define WO_HLLH 0
#define WO_HH   32768
#define WO_SPAT 49152
#define WO_QKV  65536
#define WO_QKV2 131072
#define WO_QKV3 196608
#define WO_PROJ 262144
#define WO_FC1  327680
#define WO_FC2  589824
#define W_TOT   851968
__device__ __half g_w[W_TOT];

__device__ __forceinline__ int win_row(int p) {
    int b  = p >> 14;
    int hw = p & 16383;
    int h  = hw >> 7, w = hw & 127;
    int win = (b << 8) | ((h >> 3) << 4) | (w >> 3);
    int tok = ((h & 7) << 3) | (w & 7);
    return (win << 6) | tok;
}

// ------------------------- weight conversion -------------------------------
__global__ void conv_w_kernel(const float* w0, const float* w1, const float* w2,
                              const float* w3, const float* w4, const float* w5,
                              const float* w6, const float* w7, const float* w8,
                              __half* dst)
{
    int i = blockIdx.x * 256 + threadIdx.x;
    if (i >= W_TOT) return;
    float v;
    if      (i < WO_HH)   v = w0[i - WO_HLLH];
    else if (i < WO_SPAT) v = w1[i - WO_HH];
    else if (i < WO_QKV)  v = w2[i - WO_SPAT];
    else if (i < WO_QKV2) v = w3[i - WO_QKV];
    else if (i < WO_QKV3) v = w4[i - WO_QKV2];
    else if (i < WO_PROJ) v = w5[i - WO_QKV3];
    else if (i < WO_FC1)  v = w6[i - WO_PROJ];
    else if (i < WO_FC2)  v = w7[i - WO_FC1];
    else                  v = w8[i - WO_FC2];
    dst[i] = __float2half_rn(v);
}

// ------------------------- pack: NCHW -> [P, Cin] fp16 ---------------------
__global__ void pack_kernel(const float* __restrict__ src, __half* __restrict__ dst,
                            int Cin, int rowStride, int colOff)
{
    __shared__ float s[32][33];
    int hw0 = blockIdx.x * 32;
    int c0  = blockIdx.y * 32;
    int b   = blockIdx.z;
    int tx = threadIdx.x, ty = threadIdx.y;
#pragma unroll
    for (int i = 0; i < 4; i++)
        s[ty + 8*i][tx] = src[((size_t)(b*Cin + c0 + ty + 8*i))*HW_ + hw0 + tx];
    __syncthreads();
#pragma unroll
    for (int i = 0; i < 4; i++)
        dst[(size_t)(b*HW_ + hw0 + ty + 8*i)*rowStride + colOff + c0 + tx] =
            __float2half_rn(s[tx][ty + 8*i]);
}

// ------------------------- unpack: [P, C] -> NCHW --------------------------
__global__ void unpack_kernel(const float* __restrict__ src, float* __restrict__ dst)
{
    __shared__ float s[32][33];
    int hw0 = blockIdx.x * 32;
    int c0  = blockIdx.y * 32;
    int b   = blockIdx.z;
    int tx = threadIdx.x, ty = threadIdx.y;
#pragma unroll
    for (int i = 0; i < 4; i++)
        s[ty + 8*i][tx] = src[(size_t)(b*HW_ + hw0 + ty + 8*i)*CDIM + c0 + tx];
    __syncthreads();
#pragma unroll
    for (int i = 0; i < 4; i++)
        dst[(size_t)(b*CDIM + c0 + ty + 8*i)*HW_ + hw0 + tx] = s[tx][ty + 8*i];
}

// ------------------------- fp16 tensor-core GEMM ---------------------------
// Block 128x128, k-tile 64 halfs, 8 warps (2M x 4N), 3-stage cp.async.
#define HP 72
#define HSTAGE (128*HP)              // halfs per matrix per stage
#define GSMEM  (3 * 2 * HSTAGE * 2)  // 110592 bytes

__device__ __forceinline__ void mma_f16(float c[4], uint32_t a0, uint32_t a1,
                                        uint32_t a2, uint32_t a3,
                                        uint32_t b0, uint32_t b1)
{
    asm volatile(
        "mma.sync.aligned.m16n8k16.row.col.f32.f16.f16.f32 "
        "{%0,%1,%2,%3}, {%4,%5,%6,%7}, {%8,%9}, {%0,%1,%2,%3};\n"
        : "+f"(c[0]), "+f"(c[1]), "+f"(c[2]), "+f"(c[3])
        : "r"(a0), "r"(a1), "r"(a2), "r"(a3), "r"(b0), "r"(b1));
}

__device__ __forceinline__ void ldsm4(uint32_t& r0, uint32_t& r1,
                                      uint32_t& r2, uint32_t& r3, uint32_t addr)
{
    asm volatile("ldmatrix.sync.aligned.m8n8.x4.shared.b16 {%0,%1,%2,%3}, [%4];"
                 : "=r"(r0), "=r"(r1), "=r"(r2), "=r"(r3) : "r"(addr));
}

__device__ __forceinline__ void cp16(uint32_t dst_smem, const __half* src) {
    asm volatile("cp.async.cg.shared.global [%0], [%1], 16;\n"
                 :: "r"(dst_smem), "l"(src));
}

__global__ __launch_bounds__(256, 2)
void gemm_h(const __half* __restrict__ A, const __half* __restrict__ Wm,
            const float* __restrict__ bias, const float* __restrict__ bias2,
            const float* __restrict__ res, void* __restrict__ Cout,
            int M, int N, int K, float alpha, int gelu, int out_half)
{
    extern __shared__ __half smem[];
    const uint32_t smem_base = (uint32_t)__cvta_generic_to_shared(smem);

    int bx = blockIdx.x, by = blockIdx.y;
    int tid  = threadIdx.x;
    int warp = tid >> 5, lane = tid & 31;
    int wm = warp >> 2;
    int wn = warp & 3;
    int g  = lane >> 2, c = lane & 3;

    const __half* Ab = A  + (size_t)by * 128 * K;
    const __half* Wb = Wm + (size_t)bx * 128 * K;

    float acc[4][4][4];
#pragma unroll
    for (int i = 0; i < 4; i++)
#pragma unroll
        for (int j = 0; j < 4; j++)
#pragma unroll
            for (int r = 0; r < 4; r++) acc[i][j][r] = 0.f;

    const int nk = K >> 6;
    int mrow = wm * 64;
    int ncol = wn * 32;

    // ldmatrix lane geometry
    int lr   = lane & 7;
    int aRow = mrow + lr + ((lane >> 3) & 1) * 8;
    int aCol = (lane >> 4) << 3;
    int bRow = ncol + lr + ((lane >> 4) << 3);
    int bCol = ((lane >> 3) & 1) << 3;

    auto issue = [&](int kt, int buf) {
        int k0 = kt << 6;
        uint32_t sa = smem_base + (uint32_t)(buf * 2 * HSTAGE) * 2u;
        uint32_t sb = sa + (uint32_t)HSTAGE * 2u;
#pragma unroll
        for (int i = 0; i < 4; i++) {
            int ch = tid + (i << 8);
            int row = ch >> 3;
            int c8  = (ch & 7) << 3;
            cp16(sa + (uint32_t)(row * HP + c8) * 2u, Ab + (size_t)row * K + k0 + c8);
            cp16(sb + (uint32_t)(row * HP + c8) * 2u, Wb + (size_t)row * K + k0 + c8);
        }
        asm volatile("cp.async.commit_group;\n");
    };

    issue(0, 0);
    if (nk > 1) issue(1, 1);

    for (int kt = 0; kt < nk; kt++) {
        if (kt + 1 < nk) asm volatile("cp.async.wait_group 1;\n");
        else             asm volatile("cp.async.wait_group 0;\n");
        __syncthreads();
        if (kt + 2 < nk) issue(kt + 2, (kt + 2) % 3);

        uint32_t aBase = smem_base + (uint32_t)((kt % 3) * 2 * HSTAGE) * 2u;
        uint32_t bBase = aBase + (uint32_t)HSTAGE * 2u;

#pragma unroll
        for (int ks = 0; ks < 4; ks++) {
            int k0 = ks << 4;
            uint32_t af[4][4];
#pragma unroll
            for (int mt = 0; mt < 4; mt++)
                ldsm4(af[mt][0], af[mt][1], af[mt][2], af[mt][3],
                      aBase + (uint32_t)((aRow + mt * 16) * HP + k0 + aCol) * 2u);
            uint32_t bf[4][2];
#pragma unroll
            for (int ntp = 0; ntp < 2; ntp++)
                ldsm4(bf[2*ntp][0], bf[2*ntp][1], bf[2*ntp+1][0], bf[2*ntp+1][1],
                      bBase + (uint32_t)((bRow + ntp * 16) * HP + k0 + bCol) * 2u);
#pragma unroll
            for (int mt = 0; mt < 4; mt++)
#pragma unroll
                for (int nt = 0; nt < 4; nt++)
                    mma_f16(acc[mt][nt], af[mt][0], af[mt][1], af[mt][2], af[mt][3],
                            bf[nt][0], bf[nt][1]);
        }
        __syncthreads();
    }

    float* Cf = (float*)Cout;
    __half* Ch = (__half*)Cout;
#pragma unroll
    for (int mt = 0; mt < 4; mt++) {
#pragma unroll
        for (int nt = 0; nt < 4; nt++) {
            int row = by * 128 + wm * 64 + mt * 16 + g;
            int col = bx * 128 + wn * 32 + nt * 8 + 2 * c;
            const float* bp = bias;
            int cadj = col;
            if (bias2 && col >= 256) { bp = bias2; cadj = col - 256; }
#pragma unroll
            for (int half_ = 0; half_ < 2; half_++) {
                int rr = row + half_ * 8;
                float v0 = (acc[mt][nt][half_*2+0] + bp[cadj])     * alpha;
                float v1 = (acc[mt][nt][half_*2+1] + bp[cadj + 1]) * alpha;
                if (gelu) {
                    v0 = 0.5f * v0 * (1.0f + erff(v0 * 0.70710678118654752f));
                    v1 = 0.5f * v1 * (1.0f + erff(v1 * 0.70710678118654752f));
                }
                if (res) {
                    v0 += res[(size_t)rr * N + col];
                    v1 += res[(size_t)rr * N + col + 1];
                }
                if (out_half) {
                    __half2 o = __floats2half2_rn(v0, v1);
                    *(__half2*)&Ch[(size_t)rr * N + col] = o;
                } else {
                    float2 o = {v0, v1};
                    *(float2*)&Cf[(size_t)rr * N + col] = o;
                }
            }
        }
    }
}

// ------------------------- LayerNorm + window partition (fp16 in/out) ------
__global__ void ln_part_kernel(const __half* __restrict__ x, const float* __restrict__ g,
                               const float* __restrict__ b, __half* __restrict__ out,
                               int to_window)
{
    int warp = threadIdx.x >> 5, lane = threadIdx.x & 31;
    int p = blockIdx.x * 8 + warp;
    const __half* row = x + (size_t)p * CDIM;
    int c0 = lane * 8;
    uint4 w = *(const uint4*)(row + c0);
    __half2* hw = (__half2*)&w;
    float v[8];
#pragma unroll
    for (int i = 0; i < 4; i++) {
        float2 f = __half22float2(hw[i]);
        v[2*i] = f.x; v[2*i+1] = f.y;
    }
    float s = 0.f, sq = 0.f;
#pragma unroll
    for (int i = 0; i < 8; i++) { s += v[i]; sq += v[i]*v[i]; }
#pragma unroll
    for (int o = 16; o; o >>= 1) {
        s  += __shfl_xor_sync(0xffffffffu, s,  o);
        sq += __shfl_xor_sync(0xffffffffu, sq, o);
    }
    float mean = s * (1.0f/CDIM);
    float var  = sq * (1.0f/CDIM) - mean*mean;
    float rstd = rsqrtf(var + 1e-5f);
    int r = to_window ? win_row(p) : p;
    uint4 o4;
    __half2* ho = (__half2*)&o4;
#pragma unroll
    for (int i = 0; i < 4; i++)
        ho[i] = __floats2half2_rn((v[2*i]  -mean)*rstd*g[c0+2*i]   + b[c0+2*i],
                                  (v[2*i+1]-mean)*rstd*g[c0+2*i+1] + b[c0+2*i+1]);
    *(uint4*)(out + (size_t)r * CDIM + c0) = o4;
}

// ------------------------- residual + LN2 (window-reverse) -----------------
__global__ void res_ln2_kernel(const __half* __restrict__ proj, const float* __restrict__ sc,
                               const float* __restrict__ g, const float* __restrict__ b,
                               float* __restrict__ zt, __half* __restrict__ ln2)
{
    int warp = threadIdx.x >> 5, lane = threadIdx.x & 31;
    int p = blockIdx.x * 8 + warp;
    int r = win_row(p);
    int c0 = lane * 8;
    uint4 wp = *(const uint4*)(proj + (size_t)r * CDIM + c0);
    __half2* hp2 = (__half2*)&wp;
    float4 s0 = *(const float4*)(sc + (size_t)p*CDIM + c0);
    float4 s1 = *(const float4*)(sc + (size_t)p*CDIM + c0 + 4);
    float sa[8] = {s0.x,s0.y,s0.z,s0.w, s1.x,s1.y,s1.z,s1.w};
    float v[8];
#pragma unroll
    for (int i = 0; i < 4; i++) {
        float2 f = __half22float2(hp2[i]);
        v[2*i] = f.x + sa[2*i]; v[2*i+1] = f.y + sa[2*i+1];
    }
    float4 z0 = {v[0],v[1],v[2],v[3]};
    float4 z1 = {v[4],v[5],v[6],v[7]};
    *(float4*)(zt + (size_t)p*CDIM + c0)     = z0;
    *(float4*)(zt + (size_t)p*CDIM + c0 + 4) = z1;
    float s = 0.f, sq = 0.f;
#pragma unroll
    for (int i = 0; i < 8; i++) { s += v[i]; sq += v[i]*v[i]; }
#pragma unroll
    for (int o = 16; o; o >>= 1) {
        s  += __shfl_xor_sync(0xffffffffu, s,  o);
        sq += __shfl_xor_sync(0xffffffffu, sq, o);
    }
    float mean = s * (1.0f/CDIM);
    float var  = sq * (1.0f/CDIM) - mean*mean;
    float rstd = rsqrtf(var + 1e-5f);
    uint4 o4;
    __half2* ho = (__half2*)&o4;
#pragma unroll
    for (int i = 0; i < 4; i++)
        ho[i] = __floats2half2_rn((v[2*i]  -mean)*rstd*g[c0+2*i]   + b[c0+2*i],
                                  (v[2*i+1]-mean)*rstd*g[c0+2*i+1] + b[c0+2*i+1]);
    *(uint4*)(ln2 + (size_t)p * CDIM + c0) = o4;
}

// ------------------------- mma windowed attention --------------------------
// q in [P,256]; k/v interleaved in kv [P,512] (k cols 0..255, v cols 256..511)
__global__ __launch_bounds__(256)
void attn_kernel(const __half* __restrict__ q, const __half* __restrict__ kv,
                 const float* __restrict__ rpb, __half* __restrict__ out)
{
    __shared__ __half qs [64*72];
    __shared__ __half ks_[64*72];
    __shared__ __half vst[2*32*72];
    __shared__ float  rpbs[1800];
    int win = blockIdx.x, hp = blockIdx.y;
    int tid = threadIdx.x;
    size_t qbase  = (size_t)win * 64 * CDIM + hp * 64;
    size_t kvbase = (size_t)win * 64 * 512  + hp * 64;

    for (int i = tid; i < 2048; i += 256) {
        int n = i >> 5, j = i & 31;
        *(uint32_t*)(qs  + n*72 + 2*j) = *(const uint32_t*)(q  + qbase  + (size_t)n*CDIM + 2*j);
        *(uint32_t*)(ks_ + n*72 + 2*j) = *(const uint32_t*)(kv + kvbase + (size_t)n*512  + 2*j);
        __half2 wv = *(const __half2*)(kv + kvbase + 256 + (size_t)n*512 + 2*j);
        int dl = 2*j, hl = dl >> 5, dd = dl & 31;
        vst[hl*2304 + dd*72 + n]     = __low2half(wv);
        vst[hl*2304 + (dd+1)*72 + n] = __high2half(wv);
    }
    for (int i = tid; i < 1800; i += 256) rpbs[i] = rpb[i];
    __syncthreads();

    int warp = tid >> 5, lane = tid & 31;
    int hl = warp >> 2, mq = warp & 3;
    int h  = hp * 2 + hl;
    int g  = lane >> 2, c = lane & 3;

    float sacc[8][4];
#pragma unroll
    for (int nt = 0; nt < 8; nt++)
#pragma unroll
        for (int r = 0; r < 4; r++) sacc[nt][r] = 0.f;

#pragma unroll
    for (int ks = 0; ks < 2; ks++) {
        int kc = hl*32 + ks*16 + 2*c;
        int r0 = mq*16 + g;
        uint32_t a0 = *(const uint32_t*)&qs[r0*72 + kc];
        uint32_t a1 = *(const uint32_t*)&qs[(r0+8)*72 + kc];
        uint32_t a2 = *(const uint32_t*)&qs[r0*72 + kc + 8];
        uint32_t a3 = *(const uint32_t*)&qs[(r0+8)*72 + kc + 8];
#pragma unroll
        for (int nt = 0; nt < 8; nt++) {
            int n0 = nt*8 + g;
            uint32_t b0 = *(const uint32_t*)&ks_[n0*72 + kc];
            uint32_t b1 = *(const uint32_t*)&ks_[n0*72 + kc + 8];
            mma_f16(sacc[nt], a0, a1, a2, a3, b0, b1);
        }
    }

    int dj0 = g - 2*c + 7, dj1 = dj0 - 1;
#pragma unroll
    for (int nt = 0; nt < 8; nt++) {
        int di0 = mq*2 - nt + 7, di1 = di0 + 1;
        sacc[nt][0] += rpbs[(di0*15 + dj0)*NHEAD + h];
        sacc[nt][1] += rpbs[(di0*15 + dj1)*NHEAD + h];
        sacc[nt][2] += rpbs[(di1*15 + dj0)*NHEAD + h];
        sacc[nt][3] += rpbs[(di1*15 + dj1)*NHEAD + h];
    }

    float mxA = -1e30f, mxB = -1e30f;
#pragma unroll
    for (int nt = 0; nt < 8; nt++) {
        mxA = fmaxf(mxA, fmaxf(sacc[nt][0], sacc[nt][1]));
        mxB = fmaxf(mxB, fmaxf(sacc[nt][2], sacc[nt][3]));
    }
#pragma unroll
    for (int o = 1; o <= 2; o <<= 1) {
        mxA = fmaxf(mxA, __shfl_xor_sync(0xffffffffu, mxA, o));
        mxB = fmaxf(mxB, __shfl_xor_sync(0xffffffffu, mxB, o));
    }
    float smA = 0.f, smB = 0.f;
#pragma unroll
    for (int nt = 0; nt < 8; nt++) {
        sacc[nt][0] = expf(sacc[nt][0] - mxA); smA += sacc[nt][0];
        sacc[nt][1] = expf(sacc[nt][1] - mxA); smA += sacc[nt][1];
        sacc[nt][2] = expf(sacc[nt][2] - mxB); smB += sacc[nt][2];
        sacc[nt][3] = expf(sacc[nt][3] - mxB); smB += sacc[nt][3];
    }
#pragma unroll
    for (int o = 1; o <= 2; o <<= 1) {
        smA += __shfl_xor_sync(0xffffffffu, smA, o);
        smB += __shfl_xor_sync(0xffffffffu, smB, o);
    }
    float ivA = 1.0f / smA, ivB = 1.0f / smB;

    uint32_t pf[4][4];
#pragma unroll
    for (int kt = 0; kt < 4; kt++) {
        __half2 t;
        t = __floats2half2_rn(sacc[2*kt][0]*ivA,   sacc[2*kt][1]*ivA);   pf[kt][0] = *(uint32_t*)&t;
        t = __floats2half2_rn(sacc[2*kt][2]*ivB,   sacc[2*kt][3]*ivB);   pf[kt][1] = *(uint32_t*)&t;
        t = __floats2half2_rn(sacc[2*kt+1][0]*ivA, sacc[2*kt+1][1]*ivA); pf[kt][2] = *(uint32_t*)&t;
        t = __floats2half2_rn(sacc[2*kt+1][2]*ivB, sacc[2*kt+1][3]*ivB); pf[kt][3] = *(uint32_t*)&t;
    }

    float oacc[4][4];
#pragma unroll
    for (int nt = 0; nt < 4; nt++)
#pragma unroll
        for (int r = 0; r < 4; r++) oacc[nt][r] = 0.f;
    const __half* vh = vst + hl*2304;
#pragma unroll
    for (int kt = 0; kt < 4; kt++) {
#pragma unroll
        for (int nt = 0; nt < 4; nt++) {
            int n0 = nt*8 + g;
            uint32_t b0 = *(const uint32_t*)&vh[n0*72 + kt*16 + 2*c];
            uint32_t b1 = *(const uint32_t*)&vh[n0*72 + kt*16 + 2*c + 8];
            mma_f16(oacc[nt], pf[kt][0], pf[kt][1], pf[kt][2], pf[kt][3], b0, b1);
        }
    }

    __half* orow = out + (size_t)(win*64 + mq*16 + g) * CDIM + h*HD;
#pragma unroll
    for (int nt = 0; nt < 4; nt++) {
        __half2 o0 = __floats2half2_rn(oacc[nt][0], oacc[nt][1]);
        __half2 o1 = __floats2half2_rn(oacc[nt][2], oacc[nt][3]);
        *(__half2*)(orow + nt*8 + 2*c)          = o0;
        *(__half2*)(orow + 8*CDIM + nt*8 + 2*c) = o1;
    }
}

// ---------------------------------------------------------------------------
extern "C" void kernel_launch(void* const* d_in, const int* in_sizes, int n_in,
                              void* d_out, int out_size)
{
    const float* LH      = (const float*)d_in[0];
    const float* HL      = (const float*)d_in[1];
    const float* HH      = (const float*)d_in[2];
    const float* Spat    = (const float*)d_in[3];
    const float* w_hllh  = (const float*)d_in[4];
    const float* b_hllh  = (const float*)d_in[5];
    const float* w_hh    = (const float*)d_in[6];
    const float* b_hh    = (const float*)d_in[7];
    const float* w_spat  = (const float*)d_in[8];
    const float* b_spat  = (const float*)d_in[9];
    const float* ln1x_g  = (const float*)d_in[10];
    const float* ln1x_b  = (const float*)d_in[11];
    const float* ln1y_g  = (const float*)d_in[12];
    const float* ln1y_b  = (const float*)d_in[13];
    const float* qkv_w   = (const float*)d_in[14];
    const float* qkv_b   = (const float*)d_in[15];
    const float* qkv2_w  = (const float*)d_in[16];
    const float* qkv2_b  = (const float*)d_in[17];
    const float* qkv3_w  = (const float*)d_in[18];
    const float* qkv3_b  = (const float*)d_in[19];
    const float* proj_w  = (const float*)d_in[20];
    const float* proj_b  = (const float*)d_in[21];
    const float* rpb     = (const float*)d_in[22];
    const float* ln2_g   = (const float*)d_in[23];
    const float* ln2_b   = (const float*)d_in[24];
    const float* fc1_w   = (const float*)d_in[25];
    const float* fc1_b   = (const float*)d_in[26];
    const float* fc2_w   = (const float*)d_in[27];
    const float* fc2_b   = (const float*)d_in[28];
    float* out = (float*)d_out;

    __half *inx, *iny, *inz, *x, *y, *xn, *yn, *q, *kv, *ao, *po, *ln2h, *hbuf, *wbuf;
    float *shrt, *zt, *zt2;
    cudaGetSymbolAddress((void**)&inx,  g_inx);
    cudaGetSymbolAddress((void**)&iny,  g_iny);
    cudaGetSymbolAddress((void**)&inz,  g_inz);
    cudaGetSymbolAddress((void**)&x,    g_x);
    cudaGetSymbolAddress((void**)&y,    g_y);
    cudaGetSymbolAddress((void**)&xn,   g_xn);
    cudaGetSymbolAddress((void**)&yn,   g_yn);
    cudaGetSymbolAddress((void**)&shrt, g_short);
    cudaGetSymbolAddress((void**)&q,    g_q);
    cudaGetSymbolAddress((void**)&kv,   g_kv);
    cudaGetSymbolAddress((void**)&ao,   g_ao);
    cudaGetSymbolAddress((void**)&po,   g_po);
    cudaGetSymbolAddress((void**)&zt,   g_zt);
    cudaGetSymbolAddress((void**)&ln2h, g_ln2);
    cudaGetSymbolAddress((void**)&hbuf, g_h);
    cudaGetSymbolAddress((void**)&zt2,  g_zt2);
    cudaGetSymbolAddress((void**)&wbuf, g_w);

    static int smem_set = 0;
    if (!smem_set) {
        cudaFuncSetAttribute(gemm_h, cudaFuncAttributeMaxDynamicSharedMemorySize, GSMEM);
        smem_set = 1;
    }

    dim3 tb(32, 8);
    const int M = P_TOT;
    const float qscale = 0.17677669529663688f;

    conv_w_kernel<<<(W_TOT + 255)/256, 256>>>(w_hllh, w_hh, w_spat, qkv_w, qkv2_w,
                                              qkv3_w, proj_w, fc1_w, fc2_w, wbuf);

    pack_kernel<<<dim3(HW_/32, 2, B_), tb>>>(LH,   inx, 64, 128, 0);
    pack_kernel<<<dim3(HW_/32, 2, B_), tb>>>(HL,   inx, 64, 128, 64);
    pack_kernel<<<dim3(HW_/32, 2, B_), tb>>>(HH,   inz, 64, 64, 0);
    pack_kernel<<<dim3(HW_/32, 2, B_), tb>>>(Spat, iny, 64, 64, 0);

    gemm_h<<<dim3(2, M/128), 256, GSMEM>>>(inx, wbuf+WO_HLLH, b_hllh, nullptr, nullptr, x,    M, 256, 128, 1.f, 0, 1);
    gemm_h<<<dim3(2, M/128), 256, GSMEM>>>(inz, wbuf+WO_HH,   b_hh,   nullptr, nullptr, shrt, M, 256, 64,  1.f, 0, 0);
    gemm_h<<<dim3(2, M/128), 256, GSMEM>>>(iny, wbuf+WO_SPAT, b_spat, nullptr, nullptr, y,    M, 256, 64,  1.f, 0, 1);

    ln_part_kernel<<<M/8, 256>>>(x, ln1x_g, ln1x_b, xn, 1);
    ln_part_kernel<<<M/8, 256>>>(y, ln1y_g, ln1y_b, yn, 1);

    // q projection; fused k|v projection into kv [P,512]
    gemm_h<<<dim3(2, M/128), 256, GSMEM>>>(xn, wbuf+WO_QKV,  qkv_b,  nullptr, nullptr, q,  M, 256, 256, qscale, 0, 1);
    gemm_h<<<dim3(4, M/128), 256, GSMEM>>>(yn, wbuf+WO_QKV2, qkv2_b, qkv3_b,  nullptr, kv, M, 512, 256, 1.f, 0, 1);

    attn_kernel<<<dim3(2048, NHEAD/2), 256>>>(q, kv, rpb, ao);

    gemm_h<<<dim3(2, M/128), 256, GSMEM>>>(ao, wbuf+WO_PROJ, proj_b, nullptr, nullptr, po, M, 256, 256, 1.f, 0, 1);

    res_ln2_kernel<<<M/8, 256>>>(po, shrt, ln2_g, ln2_b, zt, ln2h);

    gemm_h<<<dim3(8, M/128), 256, GSMEM>>>(ln2h, wbuf+WO_FC1, fc1_b, nullptr, nullptr, hbuf, M, HID, 256, 1.f, 1, 1);
    gemm_h<<<dim3(2, M/128), 256, GSMEM>>>(hbuf, wbuf+WO_FC2, fc2_b, nullptr, zt,      zt2,  M, 256, HID, 1.f, 0, 0);

    unpack_kernel<<<dim3(HW_/32, 8, B_), tb>>>(zt2, out);
}

// round 8
// speedup vs baseline: 1.4570x; 1.4570x over previous
#include <cuda_runtime.h>
#include <cuda_fp16.h>
#include <math.h>
#include <stdint.h>

// ---------------------------------------------------------------------------
// WaveletSwinTransformerBlock — fp16 mma GEMMs (R5 structure) + fused kv GEMM
// ---------------------------------------------------------------------------

#define B_     8
#define H_     128
#define W_     128
#define HW_    (H_*W_)           // 16384
#define P_TOT  (B_*HW_)          // 131072
#define CDIM   256
#define NHEAD  8
#define HD     32
#define HID    1024

// ------------------------- scratch buffers (static) ------------------------
__device__ __half g_inx[(size_t)P_TOT*128];
__device__ __half g_iny[(size_t)P_TOT*64];
__device__ __half g_inz[(size_t)P_TOT*64];
__device__ __half g_x    [(size_t)P_TOT*CDIM];
__device__ __half g_y    [(size_t)P_TOT*CDIM];
__device__ __half g_xn   [(size_t)P_TOT*CDIM];
__device__ __half g_yn   [(size_t)P_TOT*CDIM];
__device__ float  g_short[(size_t)P_TOT*CDIM];
__device__ __half g_q    [(size_t)P_TOT*CDIM];
__device__ __half g_kv   [(size_t)P_TOT*512];
__device__ __half g_ao   [(size_t)P_TOT*CDIM];
__device__ __half g_po   [(size_t)P_TOT*CDIM];
__device__ float  g_zt   [(size_t)P_TOT*CDIM];
__device__ __half g_ln2  [(size_t)P_TOT*CDIM];
__device__ __half g_h    [(size_t)P_TOT*HID];
__device__ float  g_zt2  [(size_t)P_TOT*CDIM];

// fp16 weights, concatenated
#define WO_HLLH 0
#define WO_HH   32768
#define WO_SPAT 49152
#define WO_QKV  65536
#define WO_QKV2 131072
#define WO_QKV3 196608
#define WO_PROJ 262144
#define WO_FC1  327680
#define WO_FC2  589824
#define W_TOT   851968
__device__ __half g_w[W_TOT];

__device__ __forceinline__ int win_row(int p) {
    int b  = p >> 14;
    int hw = p & 16383;
    int h  = hw >> 7, w = hw & 127;
    int win = (b << 8) | ((h >> 3) << 4) | (w >> 3);
    int tok = ((h & 7) << 3) | (w & 7);
    return (win << 6) | tok;
}

// ------------------------- weight conversion -------------------------------
__global__ void conv_w_kernel(const float* w0, const float* w1, const float* w2,
                              const float* w3, const float* w4, const float* w5,
                              const float* w6, const float* w7, const float* w8,
                              __half* dst)
{
    int i = blockIdx.x * 256 + threadIdx.x;
    if (i >= W_TOT) return;
    float v;
    if      (i < WO_HH)   v = w0[i - WO_HLLH];
    else if (i < WO_SPAT) v = w1[i - WO_HH];
    else if (i < WO_QKV)  v = w2[i - WO_SPAT];
    else if (i < WO_QKV2) v = w3[i - WO_QKV];
    else if (i < WO_QKV3) v = w4[i - WO_QKV2];
    else if (i < WO_PROJ) v = w5[i - WO_QKV3];
    else if (i < WO_FC1)  v = w6[i - WO_PROJ];
    else if (i < WO_FC2)  v = w7[i - WO_FC1];
    else                  v = w8[i - WO_FC2];
    dst[i] = __float2half_rn(v);
}

// ------------------------- pack: NCHW -> [P, Cin] fp16 ---------------------
__global__ void pack_kernel(const float* __restrict__ src, __half* __restrict__ dst,
                            int Cin, int rowStride, int colOff)
{
    __shared__ float s[32][33];
    int hw0 = blockIdx.x * 32;
    int c0  = blockIdx.y * 32;
    int b   = blockIdx.z;
    int tx = threadIdx.x, ty = threadIdx.y;
#pragma unroll
    for (int i = 0; i < 4; i++)
        s[ty + 8*i][tx] = src[((size_t)(b*Cin + c0 + ty + 8*i))*HW_ + hw0 + tx];
    __syncthreads();
#pragma unroll
    for (int i = 0; i < 4; i++)
        dst[(size_t)(b*HW_ + hw0 + ty + 8*i)*rowStride + colOff + c0 + tx] =
            __float2half_rn(s[tx][ty + 8*i]);
}

// ------------------------- unpack: [P, C] -> NCHW --------------------------
__global__ void unpack_kernel(const float* __restrict__ src, float* __restrict__ dst)
{
    __shared__ float s[32][33];
    int hw0 = blockIdx.x * 32;
    int c0  = blockIdx.y * 32;
    int b   = blockIdx.z;
    int tx = threadIdx.x, ty = threadIdx.y;
#pragma unroll
    for (int i = 0; i < 4; i++)
        s[ty + 8*i][tx] = src[(size_t)(b*HW_ + hw0 + ty + 8*i)*CDIM + c0 + tx];
    __syncthreads();
#pragma unroll
    for (int i = 0; i < 4; i++)
        dst[(size_t)(b*CDIM + c0 + ty + 8*i)*HW_ + hw0 + tx] = s[tx][ty + 8*i];
}

// ------------------------- fp16 tensor-core GEMM ---------------------------
// R5 structure: block 128x128, k-tile 64 halfs, 2-stage cp.async,
// scalar smem fragment loads, 8 warps (2M x 4N).
#define HP 72
#define HSTAGE (128*HP)
#define GSMEM  (2 * 2 * HSTAGE * 2)  // 73728 bytes

__device__ __forceinline__ void mma_f16(float c[4], uint32_t a0, uint32_t a1,
                                        uint32_t a2, uint32_t a3,
                                        uint32_t b0, uint32_t b1)
{
    asm volatile(
        "mma.sync.aligned.m16n8k16.row.col.f32.f16.f16.f32 "
        "{%0,%1,%2,%3}, {%4,%5,%6,%7}, {%8,%9}, {%0,%1,%2,%3};\n"
        : "+f"(c[0]), "+f"(c[1]), "+f"(c[2]), "+f"(c[3])
        : "r"(a0), "r"(a1), "r"(a2), "r"(a3), "r"(b0), "r"(b1));
}

__device__ __forceinline__ void cp16(uint32_t dst_smem, const __half* src) {
    asm volatile("cp.async.cg.shared.global [%0], [%1], 16;\n"
                 :: "r"(dst_smem), "l"(src));
}

__global__ __launch_bounds__(256, 2)
void gemm_h(const __half* __restrict__ A, const __half* __restrict__ Wm,
            const float* __restrict__ bias, const float* __restrict__ bias2,
            const float* __restrict__ res, void* __restrict__ Cout,
            int M, int N, int K, float alpha, int gelu, int out_half)
{
    extern __shared__ __half smem[];
    const uint32_t smem_base = (uint32_t)__cvta_generic_to_shared(smem);

    int bx = blockIdx.x, by = blockIdx.y;
    int tid  = threadIdx.x;
    int warp = tid >> 5, lane = tid & 31;
    int wm = warp >> 2;
    int wn = warp & 3;
    int g  = lane >> 2, c = lane & 3;

    const __half* Ab = A  + (size_t)by * 128 * K;
    const __half* Wb = Wm + (size_t)bx * 128 * K;

    float acc[4][4][4];
#pragma unroll
    for (int i = 0; i < 4; i++)
#pragma unroll
        for (int j = 0; j < 4; j++)
#pragma unroll
            for (int r = 0; r < 4; r++) acc[i][j][r] = 0.f;

    const int nk = K >> 6;

    auto issue = [&](int kt, int buf) {
        int k0 = kt << 6;
        uint32_t sa = smem_base + (uint32_t)(buf * 2 * HSTAGE) * 2u;
        uint32_t sb = sa + (uint32_t)HSTAGE * 2u;
#pragma unroll
        for (int i = 0; i < 4; i++) {
            int ch = tid + (i << 8);
            int row = ch >> 3;
            int c8  = (ch & 7) << 3;
            cp16(sa + (uint32_t)(row * HP + c8) * 2u, Ab + (size_t)row * K + k0 + c8);
            cp16(sb + (uint32_t)(row * HP + c8) * 2u, Wb + (size_t)row * K + k0 + c8);
        }
        asm volatile("cp.async.commit_group;\n");
    };

    issue(0, 0);

    for (int kt = 0; kt < nk; kt++) {
        asm volatile("cp.async.wait_group 0;\n");
        __syncthreads();
        if (kt + 1 < nk) issue(kt + 1, (kt + 1) & 1);

        const __half* As = smem + (kt & 1) * 2 * HSTAGE;
        const __half* Bs = As + HSTAGE;
        int mrow = wm * 64;
        int ncol = wn * 32;

#pragma unroll
        for (int ks = 0; ks < 4; ks++) {
            int k0 = ks << 4;
            uint32_t af[4][4];
#pragma unroll
            for (int mt = 0; mt < 4; mt++) {
                int r0 = mrow + mt * 16 + g;
                af[mt][0] = *(const uint32_t*)&As[r0 * HP + k0 + 2*c];
                af[mt][1] = *(const uint32_t*)&As[(r0 + 8) * HP + k0 + 2*c];
                af[mt][2] = *(const uint32_t*)&As[r0 * HP + k0 + 2*c + 8];
                af[mt][3] = *(const uint32_t*)&As[(r0 + 8) * HP + k0 + 2*c + 8];
            }
            uint32_t bf[4][2];
#pragma unroll
            for (int nt = 0; nt < 4; nt++) {
                int n0 = ncol + nt * 8 + g;
                bf[nt][0] = *(const uint32_t*)&Bs[n0 * HP + k0 + 2*c];
                bf[nt][1] = *(const uint32_t*)&Bs[n0 * HP + k0 + 2*c + 8];
            }
#pragma unroll
            for (int mt = 0; mt < 4; mt++)
#pragma unroll
                for (int nt = 0; nt < 4; nt++)
                    mma_f16(acc[mt][nt], af[mt][0], af[mt][1], af[mt][2], af[mt][3],
                            bf[nt][0], bf[nt][1]);
        }
        __syncthreads();
    }

    float* Cf = (float*)Cout;
    __half* Ch = (__half*)Cout;
#pragma unroll
    for (int mt = 0; mt < 4; mt++) {
#pragma unroll
        for (int nt = 0; nt < 4; nt++) {
            int row = by * 128 + wm * 64 + mt * 16 + g;
            int col = bx * 128 + wn * 32 + nt * 8 + 2 * c;
            const float* bp = bias;
            int cadj = col;
            if (bias2 && col >= 256) { bp = bias2; cadj = col - 256; }
#pragma unroll
            for (int half_ = 0; half_ < 2; half_++) {
                int rr = row + half_ * 8;
                float v0 = (acc[mt][nt][half_*2+0] + bp[cadj])     * alpha;
                float v1 = (acc[mt][nt][half_*2+1] + bp[cadj + 1]) * alpha;
                if (gelu) {
                    v0 = 0.5f * v0 * (1.0f + erff(v0 * 0.70710678118654752f));
                    v1 = 0.5f * v1 * (1.0f + erff(v1 * 0.70710678118654752f));
                }
                if (res) {
                    v0 += res[(size_t)rr * N + col];
                    v1 += res[(size_t)rr * N + col + 1];
                }
                if (out_half) {
                    __half2 o = __floats2half2_rn(v0, v1);
                    *(__half2*)&Ch[(size_t)rr * N + col] = o;
                } else {
                    float2 o = {v0, v1};
                    *(float2*)&Cf[(size_t)rr * N + col] = o;
                }
            }
        }
    }
}

// ------------------------- LayerNorm + window partition (fp16 in/out) ------
__global__ void ln_part_kernel(const __half* __restrict__ x, const float* __restrict__ g,
                               const float* __restrict__ b, __half* __restrict__ out,
                               int to_window)
{
    int warp = threadIdx.x >> 5, lane = threadIdx.x & 31;
    int p = blockIdx.x * 8 + warp;
    const __half* row = x + (size_t)p * CDIM;
    int c0 = lane * 8;
    uint4 w = *(const uint4*)(row + c0);
    __half2* hw = (__half2*)&w;
    float v[8];
#pragma unroll
    for (int i = 0; i < 4; i++) {
        float2 f = __half22float2(hw[i]);
        v[2*i] = f.x; v[2*i+1] = f.y;
    }
    float s = 0.f, sq = 0.f;
#pragma unroll
    for (int i = 0; i < 8; i++) { s += v[i]; sq += v[i]*v[i]; }
#pragma unroll
    for (int o = 16; o; o >>= 1) {
        s  += __shfl_xor_sync(0xffffffffu, s,  o);
        sq += __shfl_xor_sync(0xffffffffu, sq, o);
    }
    float mean = s * (1.0f/CDIM);
    float var  = sq * (1.0f/CDIM) - mean*mean;
    float rstd = rsqrtf(var + 1e-5f);
    int r = to_window ? win_row(p) : p;
    uint4 o4;
    __half2* ho = (__half2*)&o4;
#pragma unroll
    for (int i = 0; i < 4; i++)
        ho[i] = __floats2half2_rn((v[2*i]  -mean)*rstd*g[c0+2*i]   + b[c0+2*i],
                                  (v[2*i+1]-mean)*rstd*g[c0+2*i+1] + b[c0+2*i+1]);
    *(uint4*)(out + (size_t)r * CDIM + c0) = o4;
}

// ------------------------- residual + LN2 (window-reverse) -----------------
__global__ void res_ln2_kernel(const __half* __restrict__ proj, const float* __restrict__ sc,
                               const float* __restrict__ g, const float* __restrict__ b,
                               float* __restrict__ zt, __half* __restrict__ ln2)
{
    int warp = threadIdx.x >> 5, lane = threadIdx.x & 31;
    int p = blockIdx.x * 8 + warp;
    int r = win_row(p);
    int c0 = lane * 8;
    uint4 wp = *(const uint4*)(proj + (size_t)r * CDIM + c0);
    __half2* hp2 = (__half2*)&wp;
    float4 s0 = *(const float4*)(sc + (size_t)p*CDIM + c0);
    float4 s1 = *(const float4*)(sc + (size_t)p*CDIM + c0 + 4);
    float sa[8] = {s0.x,s0.y,s0.z,s0.w, s1.x,s1.y,s1.z,s1.w};
    float v[8];
#pragma unroll
    for (int i = 0; i < 4; i++) {
        float2 f = __half22float2(hp2[i]);
        v[2*i] = f.x + sa[2*i]; v[2*i+1] = f.y + sa[2*i+1];
    }
    float4 z0 = {v[0],v[1],v[2],v[3]};
    float4 z1 = {v[4],v[5],v[6],v[7]};
    *(float4*)(zt + (size_t)p*CDIM + c0)     = z0;
    *(float4*)(zt + (size_t)p*CDIM + c0 + 4) = z1;
    float s = 0.f, sq = 0.f;
#pragma unroll
    for (int i = 0; i < 8; i++) { s += v[i]; sq += v[i]*v[i]; }
#pragma unroll
    for (int o = 16; o; o >>= 1) {
        s  += __shfl_xor_sync(0xffffffffu, s,  o);
        sq += __shfl_xor_sync(0xffffffffu, sq, o);
    }
    float mean = s * (1.0f/CDIM);
    float var  = sq * (1.0f/CDIM) - mean*mean;
    float rstd = rsqrtf(var + 1e-5f);
    uint4 o4;
    __half2* ho = (__half2*)&o4;
#pragma unroll
    for (int i = 0; i < 4; i++)
        ho[i] = __floats2half2_rn((v[2*i]  -mean)*rstd*g[c0+2*i]   + b[c0+2*i],
                                  (v[2*i+1]-mean)*rstd*g[c0+2*i+1] + b[c0+2*i+1]);
    *(uint4*)(ln2 + (size_t)p * CDIM + c0) = o4;
}

// ------------------------- mma windowed attention --------------------------
// q in [P,256]; k/v interleaved in kv [P,512] (k cols 0..255, v cols 256..511)
__global__ __launch_bounds__(256)
void attn_kernel(const __half* __restrict__ q, const __half* __restrict__ kv,
                 const float* __restrict__ rpb, __half* __restrict__ out)
{
    __shared__ __half qs [64*72];
    __shared__ __half ks_[64*72];
    __shared__ __half vst[2*32*72];
    __shared__ float  rpbs[1800];
    int win = blockIdx.x, hp = blockIdx.y;
    int tid = threadIdx.x;
    size_t qbase  = (size_t)win * 64 * CDIM + hp * 64;
    size_t kvbase = (size_t)win * 64 * 512  + hp * 64;

    for (int i = tid; i < 2048; i += 256) {
        int n = i >> 5, j = i & 31;
        *(uint32_t*)(qs  + n*72 + 2*j) = *(const uint32_t*)(q  + qbase  + (size_t)n*CDIM + 2*j);
        *(uint32_t*)(ks_ + n*72 + 2*j) = *(const uint32_t*)(kv + kvbase + (size_t)n*512  + 2*j);
        __half2 wv = *(const __half2*)(kv + kvbase + 256 + (size_t)n*512 + 2*j);
        int dl = 2*j, hl = dl >> 5, dd = dl & 31;
        vst[hl*2304 + dd*72 + n]     = __low2half(wv);
        vst[hl*2304 + (dd+1)*72 + n] = __high2half(wv);
    }
    for (int i = tid; i < 1800; i += 256) rpbs[i] = rpb[i];
    __syncthreads();

    int warp = tid >> 5, lane = tid & 31;
    int hl = warp >> 2, mq = warp & 3;
    int h  = hp * 2 + hl;
    int g  = lane >> 2, c = lane & 3;

    float sacc[8][4];
#pragma unroll
    for (int nt = 0; nt < 8; nt++)
#pragma unroll
        for (int r = 0; r < 4; r++) sacc[nt][r] = 0.f;

#pragma unroll
    for (int ks = 0; ks < 2; ks++) {
        int kc = hl*32 + ks*16 + 2*c;
        int r0 = mq*16 + g;
        uint32_t a0 = *(const uint32_t*)&qs[r0*72 + kc];
        uint32_t a1 = *(const uint32_t*)&qs[(r0+8)*72 + kc];
        uint32_t a2 = *(const uint32_t*)&qs[r0*72 + kc + 8];
        uint32_t a3 = *(const uint32_t*)&qs[(r0+8)*72 + kc + 8];
#pragma unroll
        for (int nt = 0; nt < 8; nt++) {
            int n0 = nt*8 + g;
            uint32_t b0 = *(const uint32_t*)&ks_[n0*72 + kc];
            uint32_t b1 = *(const uint32_t*)&ks_[n0*72 + kc + 8];
            mma_f16(sacc[nt], a0, a1, a2, a3, b0, b1);
        }
    }

    int dj0 = g - 2*c + 7, dj1 = dj0 - 1;
#pragma unroll
    for (int nt = 0; nt < 8; nt++) {
        int di0 = mq*2 - nt + 7, di1 = di0 + 1;
        sacc[nt][0] += rpbs[(di0*15 + dj0)*NHEAD + h];
        sacc[nt][1] += rpbs[(di0*15 + dj1)*NHEAD + h];
        sacc[nt][2] += rpbs[(di1*15 + dj0)*NHEAD + h];
        sacc[nt][3] += rpbs[(di1*15 + dj1)*NHEAD + h];
    }

    float mxA = -1e30f, mxB = -1e30f;
#pragma unroll
    for (int nt = 0; nt < 8; nt++) {
        mxA = fmaxf(mxA, fmaxf(sacc[nt][0], sacc[nt][1]));
        mxB = fmaxf(mxB, fmaxf(sacc[nt][2], sacc[nt][3]));
    }
#pragma unroll
    for (int o = 1; o <= 2; o <<= 1) {
        mxA = fmaxf(mxA, __shfl_xor_sync(0xffffffffu, mxA, o));
        mxB = fmaxf(mxB, __shfl_xor_sync(0xffffffffu, mxB, o));
    }
    float smA = 0.f, smB = 0.f;
#pragma unroll
    for (int nt = 0; nt < 8; nt++) {
        sacc[nt][0] = expf(sacc[nt][0] - mxA); smA += sacc[nt][0];
        sacc[nt][1] = expf(sacc[nt][1] - mxA); smA += sacc[nt][1];
        sacc[nt][2] = expf(sacc[nt][2] - mxB); smB += sacc[nt][2];
        sacc[nt][3] = expf(sacc[nt][3] - mxB); smB += sacc[nt][3];
    }
#pragma unroll
    for (int o = 1; o <= 2; o <<= 1) {
        smA += __shfl_xor_sync(0xffffffffu, smA, o);
        smB += __shfl_xor_sync(0xffffffffu, smB, o);
    }
    float ivA = 1.0f / smA, ivB = 1.0f / smB;

    uint32_t pf[4][4];
#pragma unroll
    for (int kt = 0; kt < 4; kt++) {
        __half2 t;
        t = __floats2half2_rn(sacc[2*kt][0]*ivA,   sacc[2*kt][1]*ivA);   pf[kt][0] = *(uint32_t*)&t;
        t = __floats2half2_rn(sacc[2*kt][2]*ivB,   sacc[2*kt][3]*ivB);   pf[kt][1] = *(uint32_t*)&t;
        t = __floats2half2_rn(sacc[2*kt+1][0]*ivA, sacc[2*kt+1][1]*ivA); pf[kt][2] = *(uint32_t*)&t;
        t = __floats2half2_rn(sacc[2*kt+1][2]*ivB, sacc[2*kt+1][3]*ivB); pf[kt][3] = *(uint32_t*)&t;
    }

    float oacc[4][4];
#pragma unroll
    for (int nt = 0; nt < 4; nt++)
#pragma unroll
        for (int r = 0; r < 4; r++) oacc[nt][r] = 0.f;
    const __half* vh = vst + hl*2304;
#pragma unroll
    for (int kt = 0; kt < 4; kt++) {
#pragma unroll
        for (int nt = 0; nt < 4; nt++) {
            int n0 = nt*8 + g;
            uint32_t b0 = *(const uint32_t*)&vh[n0*72 + kt*16 + 2*c];
            uint32_t b1 = *(const uint32_t*)&vh[n0*72 + kt*16 + 2*c + 8];
            mma_f16(oacc[nt], pf[kt][0], pf[kt][1], pf[kt][2], pf[kt][3], b0, b1);
        }
    }

    __half* orow = out + (size_t)(win*64 + mq*16 + g) * CDIM + h*HD;
#pragma unroll
    for (int nt = 0; nt < 4; nt++) {
        __half2 o0 = __floats2half2_rn(oacc[nt][0], oacc[nt][1]);
        __half2 o1 = __floats2half2_rn(oacc[nt][2], oacc[nt][3]);
        *(__half2*)(orow + nt*8 + 2*c)          = o0;
        *(__half2*)(orow + 8*CDIM + nt*8 + 2*c) = o1;
    }
}

// ---------------------------------------------------------------------------
extern "C" void kernel_launch(void* const* d_in, const int* in_sizes, int n_in,
                              void* d_out, int out_size)
{
    const float* LH      = (const float*)d_in[0];
    const float* HL      = (const float*)d_in[1];
    const float* HH      = (const float*)d_in[2];
    const float* Spat    = (const float*)d_in[3];
    const float* w_hllh  = (const float*)d_in[4];
    const float* b_hllh  = (const float*)d_in[5];
    const float* w_hh    = (const float*)d_in[6];
    const float* b_hh    = (const float*)d_in[7];
    const float* w_spat  = (const float*)d_in[8];
    const float* b_spat  = (const float*)d_in[9];
    const float* ln1x_g  = (const float*)d_in[10];
    const float* ln1x_b  = (const float*)d_in[11];
    const float* ln1y_g  = (const float*)d_in[12];
    const float* ln1y_b  = (const float*)d_in[13];
    const float* qkv_w   = (const float*)d_in[14];
    const float* qkv_b   = (const float*)d_in[15];
    const float* qkv2_w  = (const float*)d_in[16];
    const float* qkv2_b  = (const float*)d_in[17];
    const float* qkv3_w  = (const float*)d_in[18];
    const float* qkv3_b  = (const float*)d_in[19];
    const float* proj_w  = (const float*)d_in[20];
    const float* proj_b  = (const float*)d_in[21];
    const float* rpb     = (const float*)d_in[22];
    const float* ln2_g   = (const float*)d_in[23];
    const float* ln2_b   = (const float*)d_in[24];
    const float* fc1_w   = (const float*)d_in[25];
    const float* fc1_b   = (const float*)d_in[26];
    const float* fc2_w   = (const float*)d_in[27];
    const float* fc2_b   = (const float*)d_in[28];
    float* out = (float*)d_out;

    __half *inx, *iny, *inz, *x, *y, *xn, *yn, *q, *kv, *ao, *po, *ln2h, *hbuf, *wbuf;
    float *shrt, *zt, *zt2;
    cudaGetSymbolAddress((void**)&inx,  g_inx);
    cudaGetSymbolAddress((void**)&iny,  g_iny);
    cudaGetSymbolAddress((void**)&inz,  g_inz);
    cudaGetSymbolAddress((void**)&x,    g_x);
    cudaGetSymbolAddress((void**)&y,    g_y);
    cudaGetSymbolAddress((void**)&xn,   g_xn);
    cudaGetSymbolAddress((void**)&yn,   g_yn);
    cudaGetSymbolAddress((void**)&shrt, g_short);
    cudaGetSymbolAddress((void**)&q,    g_q);
    cudaGetSymbolAddress((void**)&kv,   g_kv);
    cudaGetSymbolAddress((void**)&ao,   g_ao);
    cudaGetSymbolAddress((void**)&po,   g_po);
    cudaGetSymbolAddress((void**)&zt,   g_zt);
    cudaGetSymbolAddress((void**)&ln2h, g_ln2);
    cudaGetSymbolAddress((void**)&hbuf, g_h);
    cudaGetSymbolAddress((void**)&zt2,  g_zt2);
    cudaGetSymbolAddress((void**)&wbuf, g_w);

    static int smem_set = 0;
    if (!smem_set) {
        cudaFuncSetAttribute(gemm_h, cudaFuncAttributeMaxDynamicSharedMemorySize, GSMEM);
        smem_set = 1;
    }

    dim3 tb(32, 8);
    const int M = P_TOT;
    const float qscale = 0.17677669529663688f;

    conv_w_kernel<<<(W_TOT + 255)/256, 256>>>(w_hllh, w_hh, w_spat, qkv_w, qkv2_w,
                                              qkv3_w, proj_w, fc1_w, fc2_w, wbuf);

    pack_kernel<<<dim3(HW_/32, 2, B_), tb>>>(LH,   inx, 64, 128, 0);
    pack_kernel<<<dim3(HW_/32, 2, B_), tb>>>(HL,   inx, 64, 128, 64);
    pack_kernel<<<dim3(HW_/32, 2, B_), tb>>>(HH,   inz, 64, 64, 0);
    pack_kernel<<<dim3(HW_/32, 2, B_), tb>>>(Spat, iny, 64, 64, 0);

    gemm_h<<<dim3(2, M/128), 256, GSMEM>>>(inx, wbuf+WO_HLLH, b_hllh, nullptr, nullptr, x,    M, 256, 128, 1.f, 0, 1);
    gemm_h<<<dim3(2, M/128), 256, GSMEM>>>(inz, wbuf+WO_HH,   b_hh,   nullptr, nullptr, shrt, M, 256, 64,  1.f, 0, 0);
    gemm_h<<<dim3(2, M/128), 256, GSMEM>>>(iny, wbuf+WO_SPAT, b_spat, nullptr, nullptr, y,    M, 256, 64,  1.f, 0, 1);

    ln_part_kernel<<<M/8, 256>>>(x, ln1x_g, ln1x_b, xn, 1);
    ln_part_kernel<<<M/8, 256>>>(y, ln1y_g, ln1y_b, yn, 1);

    // q projection; fused k|v projection into kv [P,512]
    gemm_h<<<dim3(2, M/128), 256, GSMEM>>>(xn, wbuf+WO_QKV,  qkv_b,  nullptr, nullptr, q,  M, 256, 256, qscale, 0, 1);
    gemm_h<<<dim3(4, M/128), 256, GSMEM>>>(yn, wbuf+WO_QKV2, qkv2_b, qkv3_b,  nullptr, kv, M, 512, 256, 1.f, 0, 1);

    attn_kernel<<<dim3(2048, NHEAD/2), 256>>>(q, kv, rpb, ao);

    gemm_h<<<dim3(2, M/128), 256, GSMEM>>>(ao, wbuf+WO_PROJ, proj_b, nullptr, nullptr, po, M, 256, 256, 1.f, 0, 1);

    res_ln2_kernel<<<M/8, 256>>>(po, shrt, ln2_g, ln2_b, zt, ln2h);

    gemm_h<<<dim3(8, M/128), 256, GSMEM>>>(ln2h, wbuf+WO_FC1, fc1_b, nullptr, nullptr, hbuf, M, HID, 256, 1.f, 1, 1);
    gemm_h<<<dim3(2, M/128), 256, GSMEM>>>(hbuf, wbuf+WO_FC2, fc2_b, nullptr, zt,      zt2,  M, 256, HID, 1.f, 0, 0);

    unpack_kernel<<<dim3(HW_/32, 8, B_), tb>>>(zt2, out);
}

// round 10
// speedup vs baseline: 1.4704x; 1.0092x over previous
#include <cuda_runtime.h>
#include <cuda_fp16.h>
#include <math.h>
#include <stdint.h>

// ---------------------------------------------------------------------------
// WaveletSwinTransformerBlock — fp16 mma GEMMs, 3-stage cp.async, 1 sync/iter
// ---------------------------------------------------------------------------

#define B_     8
#define H_     128
#define W_     128
#define HW_    (H_*W_)           // 16384
#define P_TOT  (B_*HW_)          // 131072
#define CDIM   256
#define NHEAD  8
#define HD     32
#define HID    1024

// ------------------------- scratch buffers (static) ------------------------
__device__ __half g_inx[(size_t)P_TOT*128];
__device__ __half g_iny[(size_t)P_TOT*64];
__device__ __half g_inz[(size_t)P_TOT*64];
__device__ __half g_x    [(size_t)P_TOT*CDIM];
__device__ __half g_y    [(size_t)P_TOT*CDIM];
__device__ __half g_xn   [(size_t)P_TOT*CDIM];
__device__ __half g_yn   [(size_t)P_TOT*CDIM];
__device__ float  g_short[(size_t)P_TOT*CDIM];
__device__ __half g_q    [(size_t)P_TOT*CDIM];
__device__ __half g_kv   [(size_t)P_TOT*512];
__device__ __half g_ao   [(size_t)P_TOT*CDIM];
__device__ __half g_po   [(size_t)P_TOT*CDIM];
__device__ float  g_zt   [(size_t)P_TOT*CDIM];
__device__ __half g_ln2  [(size_t)P_TOT*CDIM];
__device__ __half g_h    [(size_t)P_TOT*HID];
__device__ float  g_zt2  [(size_t)P_TOT*CDIM];

// fp16 weights, concatenated
#define WO_HLLH 0
#define WO_HH   32768
#define WO_SPAT 49152
#define WO_QKV  65536
#define WO_QKV2 131072
#define WO_QKV3 196608
#define WO_PROJ 262144
#define WO_FC1  327680
#define WO_FC2  589824
#define W_TOT   851968
__device__ __half g_w[W_TOT];

__device__ __forceinline__ int win_row(int p) {
    int b  = p >> 14;
    int hw = p & 16383;
    int h  = hw >> 7, w = hw & 127;
    int win = (b << 8) | ((h >> 3) << 4) | (w >> 3);
    int tok = ((h & 7) << 3) | (w & 7);
    return (win << 6) | tok;
}

// ------------------------- weight conversion -------------------------------
__global__ void conv_w_kernel(const float* w0, const float* w1, const float* w2,
                              const float* w3, const float* w4, const float* w5,
                              const float* w6, const float* w7, const float* w8,
                              __half* dst)
{
    int i = blockIdx.x * 256 + threadIdx.x;
    if (i >= W_TOT) return;
    float v;
    if      (i < WO_HH)   v = w0[i - WO_HLLH];
    else if (i < WO_SPAT) v = w1[i - WO_HH];
    else if (i < WO_QKV)  v = w2[i - WO_SPAT];
    else if (i < WO_QKV2) v = w3[i - WO_QKV];
    else if (i < WO_QKV3) v = w4[i - WO_QKV2];
    else if (i < WO_PROJ) v = w5[i - WO_QKV3];
    else if (i < WO_FC1)  v = w6[i - WO_PROJ];
    else if (i < WO_FC2)  v = w7[i - WO_FC1];
    else                  v = w8[i - WO_FC2];
    dst[i] = __float2half_rn(v);
}

// ------------------------- pack: NCHW -> [P, Cin] fp16 ---------------------
__global__ void pack_kernel(const float* __restrict__ src, __half* __restrict__ dst,
                            int Cin, int rowStride, int colOff)
{
    __shared__ float s[32][33];
    int hw0 = blockIdx.x * 32;
    int c0  = blockIdx.y * 32;
    int b   = blockIdx.z;
    int tx = threadIdx.x, ty = threadIdx.y;
#pragma unroll
    for (int i = 0; i < 4; i++)
        s[ty + 8*i][tx] = src[((size_t)(b*Cin + c0 + ty + 8*i))*HW_ + hw0 + tx];
    __syncthreads();
#pragma unroll
    for (int i = 0; i < 4; i++)
        dst[(size_t)(b*HW_ + hw0 + ty + 8*i)*rowStride + colOff + c0 + tx] =
            __float2half_rn(s[tx][ty + 8*i]);
}

// ------------------------- unpack: [P, C] -> NCHW --------------------------
__global__ void unpack_kernel(const float* __restrict__ src, float* __restrict__ dst)
{
    __shared__ float s[32][33];
    int hw0 = blockIdx.x * 32;
    int c0  = blockIdx.y * 32;
    int b   = blockIdx.z;
    int tx = threadIdx.x, ty = threadIdx.y;
#pragma unroll
    for (int i = 0; i < 4; i++)
        s[ty + 8*i][tx] = src[(size_t)(b*HW_ + hw0 + ty + 8*i)*CDIM + c0 + tx];
    __syncthreads();
#pragma unroll
    for (int i = 0; i < 4; i++)
        dst[(size_t)(b*CDIM + c0 + ty + 8*i)*HW_ + hw0 + tx] = s[tx][ty + 8*i];
}

// ------------------------- fp16 tensor-core GEMM ---------------------------
// Block 128x128, k-tile 64 halfs, 8 warps (2M x 4N), 3-stage cp.async,
// ONE __syncthreads per k-iteration.
#define HP 72
#define HSTAGE (128*HP)
#define GSMEM  (3 * 2 * HSTAGE * 2)  // 110592 bytes

__device__ __forceinline__ void mma_f16(float c[4], uint32_t a0, uint32_t a1,
                                        uint32_t a2, uint32_t a3,
                                        uint32_t b0, uint32_t b1)
{
    asm volatile(
        "mma.sync.aligned.m16n8k16.row.col.f32.f16.f16.f32 "
        "{%0,%1,%2,%3}, {%4,%5,%6,%7}, {%8,%9}, {%0,%1,%2,%3};\n"
        : "+f"(c[0]), "+f"(c[1]), "+f"(c[2]), "+f"(c[3])
        : "r"(a0), "r"(a1), "r"(a2), "r"(a3), "r"(b0), "r"(b1));
}

__device__ __forceinline__ void cp16(uint32_t dst_smem, const __half* src) {
    asm volatile("cp.async.cg.shared.global [%0], [%1], 16;\n"
                 :: "r"(dst_smem), "l"(src));
}

__global__ __launch_bounds__(256, 2)
void gemm_h(const __half* __restrict__ A, const __half* __restrict__ Wm,
            const float* __restrict__ bias, const float* __restrict__ bias2,
            const float* __restrict__ res, void* __restrict__ Cout,
            int M, int N, int K, float alpha, int gelu, int out_half)
{
    extern __shared__ __half smem[];
    const uint32_t smem_base = (uint32_t)__cvta_generic_to_shared(smem);

    int bx = blockIdx.x, by = blockIdx.y;
    int tid  = threadIdx.x;
    int warp = tid >> 5, lane = tid & 31;
    int wm = warp >> 2;
    int wn = warp & 3;
    int g  = lane >> 2, c = lane & 3;

    const __half* Ab = A  + (size_t)by * 128 * K;
    const __half* Wb = Wm + (size_t)bx * 128 * K;

    float acc[4][4][4];
#pragma unroll
    for (int i = 0; i < 4; i++)
#pragma unroll
        for (int j = 0; j < 4; j++)
#pragma unroll
            for (int r = 0; r < 4; r++) acc[i][j][r] = 0.f;

    const int nk = K >> 6;

    auto issue = [&](int kt, int buf) {
        int k0 = kt << 6;
        uint32_t sa = smem_base + (uint32_t)(buf * 2 * HSTAGE) * 2u;
        uint32_t sb = sa + (uint32_t)HSTAGE * 2u;
#pragma unroll
        for (int i = 0; i < 4; i++) {
            int ch = tid + (i << 8);
            int row = ch >> 3;
            int c8  = (ch & 7) << 3;
            cp16(sa + (uint32_t)(row * HP + c8) * 2u, Ab + (size_t)row * K + k0 + c8);
            cp16(sb + (uint32_t)(row * HP + c8) * 2u, Wb + (size_t)row * K + k0 + c8);
        }
        asm volatile("cp.async.commit_group;\n");
    };

    issue(0, 0);
    if (nk > 1) issue(1, 1);

    for (int kt = 0; kt < nk; kt++) {
        if (kt + 1 < nk) asm volatile("cp.async.wait_group 1;\n");
        else             asm volatile("cp.async.wait_group 0;\n");
        __syncthreads();                      // also releases buf (kt+2)%3 for reuse
        if (kt + 2 < nk) issue(kt + 2, (kt + 2) % 3);

        const __half* As = smem + (kt % 3) * 2 * HSTAGE;
        const __half* Bs = As + HSTAGE;
        int mrow = wm * 64;
        int ncol = wn * 32;

#pragma unroll
        for (int ks = 0; ks < 4; ks++) {
            int k0 = ks << 4;
            uint32_t af[4][4];
#pragma unroll
            for (int mt = 0; mt < 4; mt++) {
                int r0 = mrow + mt * 16 + g;
                af[mt][0] = *(const uint32_t*)&As[r0 * HP + k0 + 2*c];
                af[mt][1] = *(const uint32_t*)&As[(r0 + 8) * HP + k0 + 2*c];
                af[mt][2] = *(const uint32_t*)&As[r0 * HP + k0 + 2*c + 8];
                af[mt][3] = *(const uint32_t*)&As[(r0 + 8) * HP + k0 + 2*c + 8];
            }
            uint32_t bf[4][2];
#pragma unroll
            for (int nt = 0; nt < 4; nt++) {
                int n0 = ncol + nt * 8 + g;
                bf[nt][0] = *(const uint32_t*)&Bs[n0 * HP + k0 + 2*c];
                bf[nt][1] = *(const uint32_t*)&Bs[n0 * HP + k0 + 2*c + 8];
            }
#pragma unroll
            for (int mt = 0; mt < 4; mt++)
#pragma unroll
                for (int nt = 0; nt < 4; nt++)
                    mma_f16(acc[mt][nt], af[mt][0], af[mt][1], af[mt][2], af[mt][3],
                            bf[nt][0], bf[nt][1]);
        }
    }
    __syncthreads();

    float* Cf = (float*)Cout;
    __half* Ch = (__half*)Cout;
#pragma unroll
    for (int mt = 0; mt < 4; mt++) {
#pragma unroll
        for (int nt = 0; nt < 4; nt++) {
            int row = by * 128 + wm * 64 + mt * 16 + g;
            int col = bx * 128 + wn * 32 + nt * 8 + 2 * c;
            const float* bp = bias;
            int cadj = col;
            if (bias2 && col >= 256) { bp = bias2; cadj = col - 256; }
#pragma unroll
            for (int half_ = 0; half_ < 2; half_++) {
                int rr = row + half_ * 8;
                float v0 = (acc[mt][nt][half_*2+0] + bp[cadj])     * alpha;
                float v1 = (acc[mt][nt][half_*2+1] + bp[cadj + 1]) * alpha;
                if (gelu) {
                    v0 = 0.5f * v0 * (1.0f + erff(v0 * 0.70710678118654752f));
                    v1 = 0.5f * v1 * (1.0f + erff(v1 * 0.70710678118654752f));
                }
                if (res) {
                    v0 += res[(size_t)rr * N + col];
                    v1 += res[(size_t)rr * N + col + 1];
                }
                if (out_half) {
                    __half2 o = __floats2half2_rn(v0, v1);
                    *(__half2*)&Ch[(size_t)rr * N + col] = o;
                } else {
                    float2 o = {v0, v1};
                    *(float2*)&Cf[(size_t)rr * N + col] = o;
                }
            }
        }
    }
}

// ------------------------- LayerNorm + window partition (fp16 in/out) ------
__global__ void ln_part_kernel(const __half* __restrict__ x, const float* __restrict__ g,
                               const float* __restrict__ b, __half* __restrict__ out,
                               int to_window)
{
    int warp = threadIdx.x >> 5, lane = threadIdx.x & 31;
    int p = blockIdx.x * 8 + warp;
    const __half* row = x + (size_t)p * CDIM;
    int c0 = lane * 8;
    uint4 w = *(const uint4*)(row + c0);
    __half2* hw = (__half2*)&w;
    float v[8];
#pragma unroll
    for (int i = 0; i < 4; i++) {
        float2 f = __half22float2(hw[i]);
        v[2*i] = f.x; v[2*i+1] = f.y;
    }
    float s = 0.f, sq = 0.f;
#pragma unroll
    for (int i = 0; i < 8; i++) { s += v[i]; sq += v[i]*v[i]; }
#pragma unroll
    for (int o = 16; o; o >>= 1) {
        s  += __shfl_xor_sync(0xffffffffu, s,  o);
        sq += __shfl_xor_sync(0xffffffffu, sq, o);
    }
    float mean = s * (1.0f/CDIM);
    float var  = sq * (1.0f/CDIM) - mean*mean;
    float rstd = rsqrtf(var + 1e-5f);
    int r = to_window ? win_row(p) : p;
    uint4 o4;
    __half2* ho = (__half2*)&o4;
#pragma unroll
    for (int i = 0; i < 4; i++)
        ho[i] = __floats2half2_rn((v[2*i]  -mean)*rstd*g[c0+2*i]   + b[c0+2*i],
                                  (v[2*i+1]-mean)*rstd*g[c0+2*i+1] + b[c0+2*i+1]);
    *(uint4*)(out + (size_t)r * CDIM + c0) = o4;
}

// ------------------------- residual + LN2 (window-reverse) -----------------
__global__ void res_ln2_kernel(const __half* __restrict__ proj, const float* __restrict__ sc,
                               const float* __restrict__ g, const float* __restrict__ b,
                               float* __restrict__ zt, __half* __restrict__ ln2)
{
    int warp = threadIdx.x >> 5, lane = threadIdx.x & 31;
    int p = blockIdx.x * 8 + warp;
    int r = win_row(p);
    int c0 = lane * 8;
    uint4 wp = *(const uint4*)(proj + (size_t)r * CDIM + c0);
    __half2* hp2 = (__half2*)&wp;
    float4 s0 = *(const float4*)(sc + (size_t)p*CDIM + c0);
    float4 s1 = *(const float4*)(sc + (size_t)p*CDIM + c0 + 4);
    float sa[8] = {s0.x,s0.y,s0.z,s0.w, s1.x,s1.y,s1.z,s1.w};
    float v[8];
#pragma unroll
    for (int i = 0; i < 4; i++) {
        float2 f = __half22float2(hp2[i]);
        v[2*i] = f.x + sa[2*i]; v[2*i+1] = f.y + sa[2*i+1];
    }
    float4 z0 = {v[0],v[1],v[2],v[3]};
    float4 z1 = {v[4],v[5],v[6],v[7]};
    *(float4*)(zt + (size_t)p*CDIM + c0)     = z0;
    *(float4*)(zt + (size_t)p*CDIM + c0 + 4) = z1;
    float s = 0.f, sq = 0.f;
#pragma unroll
    for (int i = 0; i < 8; i++) { s += v[i]; sq += v[i]*v[i]; }
#pragma unroll
    for (int o = 16; o; o >>= 1) {
        s  += __shfl_xor_sync(0xffffffffu, s,  o);
        sq += __shfl_xor_sync(0xffffffffu, sq, o);
    }
    float mean = s * (1.0f/CDIM);
    float var  = sq * (1.0f/CDIM) - mean*mean;
    float rstd = rsqrtf(var + 1e-5f);
    uint4 o4;
    __half2* ho = (__half2*)&o4;
#pragma unroll
    for (int i = 0; i < 4; i++)
        ho[i] = __floats2half2_rn((v[2*i]  -mean)*rstd*g[c0+2*i]   + b[c0+2*i],
                                  (v[2*i+1]-mean)*rstd*g[c0+2*i+1] + b[c0+2*i+1]);
    *(uint4*)(ln2 + (size_t)p * CDIM + c0) = o4;
}

// ------------------------- mma windowed attention --------------------------
// q in [P,256]; k/v interleaved in kv [P,512] (k cols 0..255, v cols 256..511)
__global__ __launch_bounds__(256)
void attn_kernel(const __half* __restrict__ q, const __half* __restrict__ kv,
                 const float* __restrict__ rpb, __half* __restrict__ out)
{
    __shared__ __half qs [64*72];
    __shared__ __half ks_[64*72];
    __shared__ __half vst[2*32*72];
    __shared__ float  rpbs[1800];
    int win = blockIdx.x, hp = blockIdx.y;
    int tid = threadIdx.x;
    size_t qbase  = (size_t)win * 64 * CDIM + hp * 64;
    size_t kvbase = (size_t)win * 64 * 512  + hp * 64;

    for (int i = tid; i < 2048; i += 256) {
        int n = i >> 5, j = i & 31;
        *(uint32_t*)(qs  + n*72 + 2*j) = *(const uint32_t*)(q  + qbase  + (size_t)n*CDIM + 2*j);
        *(uint32_t*)(ks_ + n*72 + 2*j) = *(const uint32_t*)(kv + kvbase + (size_t)n*512  + 2*j);
        __half2 wv = *(const __half2*)(kv + kvbase + 256 + (size_t)n*512 + 2*j);
        int dl = 2*j, hl = dl >> 5, dd = dl & 31;
        vst[hl*2304 + dd*72 + n]     = __low2half(wv);
        vst[hl*2304 + (dd+1)*72 + n] = __high2half(wv);
    }
    for (int i = tid; i < 1800; i += 256) rpbs[i] = rpb[i];
    __syncthreads();

    int warp = tid >> 5, lane = tid & 31;
    int hl = warp >> 2, mq = warp & 3;
    int h  = hp * 2 + hl;
    int g  = lane >> 2, c = lane & 3;

    float sacc[8][4];
#pragma unroll
    for (int nt = 0; nt < 8; nt++)
#pragma unroll
        for (int r = 0; r < 4; r++) sacc[nt][r] = 0.f;

#pragma unroll
    for (int ks = 0; ks < 2; ks++) {
        int kc = hl*32 + ks*16 + 2*c;
        int r0 = mq*16 + g;
        uint32_t a0 = *(const uint32_t*)&qs[r0*72 + kc];
        uint32_t a1 = *(const uint32_t*)&qs[(r0+8)*72 + kc];
        uint32_t a2 = *(const uint32_t*)&qs[r0*72 + kc + 8];
        uint32_t a3 = *(const uint32_t*)&qs[(r0+8)*72 + kc + 8];
#pragma unroll
        for (int nt = 0; nt < 8; nt++) {
            int n0 = nt*8 + g;
            uint32_t b0 = *(const uint32_t*)&ks_[n0*72 + kc];
            uint32_t b1 = *(const uint32_t*)&ks_[n0*72 + kc + 8];
            mma_f16(sacc[nt], a0, a1, a2, a3, b0, b1);
        }
    }

    int dj0 = g - 2*c + 7, dj1 = dj0 - 1;
#pragma unroll
    for (int nt = 0; nt < 8; nt++) {
        int di0 = mq*2 - nt + 7, di1 = di0 + 1;
        sacc[nt][0] += rpbs[(di0*15 + dj0)*NHEAD + h];
        sacc[nt][1] += rpbs[(di0*15 + dj1)*NHEAD + h];
        sacc[nt][2] += rpbs[(di1*15 + dj0)*NHEAD + h];
        sacc[nt][3] += rpbs[(di1*15 + dj1)*NHEAD + h];
    }

    float mxA = -1e30f, mxB = -1e30f;
#pragma unroll
    for (int nt = 0; nt < 8; nt++) {
        mxA = fmaxf(mxA, fmaxf(sacc[nt][0], sacc[nt][1]));
        mxB = fmaxf(mxB, fmaxf(sacc[nt][2], sacc[nt][3]));
    }
#pragma unroll
    for (int o = 1; o <= 2; o <<= 1) {
        mxA = fmaxf(mxA, __shfl_xor_sync(0xffffffffu, mxA, o));
        mxB = fmaxf(mxB, __shfl_xor_sync(0xffffffffu, mxB, o));
    }
    float smA = 0.f, smB = 0.f;
#pragma unroll
    for (int nt = 0; nt < 8; nt++) {
        sacc[nt][0] = expf(sacc[nt][0] - mxA); smA += sacc[nt][0];
        sacc[nt][1] = expf(sacc[nt][1] - mxA); smA += sacc[nt][1];
        sacc[nt][2] = expf(sacc[nt][2] - mxB); smB += sacc[nt][2];
        sacc[nt][3] = expf(sacc[nt][3] - mxB); smB += sacc[nt][3];
    }
#pragma unroll
    for (int o = 1; o <= 2; o <<= 1) {
        smA += __shfl_xor_sync(0xffffffffu, smA, o);
        smB += __shfl_xor_sync(0xffffffffu, smB, o);
    }
    float ivA = 1.0f / smA, ivB = 1.0f / smB;

    uint32_t pf[4][4];
#pragma unroll
    for (int kt = 0; kt < 4; kt++) {
        __half2 t;
        t = __floats2half2_rn(sacc[2*kt][0]*ivA,   sacc[2*kt][1]*ivA);   pf[kt][0] = *(uint32_t*)&t;
        t = __floats2half2_rn(sacc[2*kt][2]*ivB,   sacc[2*kt][3]*ivB);   pf[kt][1] = *(uint32_t*)&t;
        t = __floats2half2_rn(sacc[2*kt+1][0]*ivA, sacc[2*kt+1][1]*ivA); pf[kt][2] = *(uint32_t*)&t;
        t = __floats2half2_rn(sacc[2*kt+1][2]*ivB, sacc[2*kt+1][3]*ivB); pf[kt][3] = *(uint32_t*)&t;
    }

    float oacc[4][4];
#pragma unroll
    for (int nt = 0; nt < 4; nt++)
#pragma unroll
        for (int r = 0; r < 4; r++) oacc[nt][r] = 0.f;
    const __half* vh = vst + hl*2304;
#pragma unroll
    for (int kt = 0; kt < 4; kt++) {
#pragma unroll
        for (int nt = 0; nt < 4; nt++) {
            int n0 = nt*8 + g;
            uint32_t b0 = *(const uint32_t*)&vh[n0*72 + kt*16 + 2*c];
            uint32_t b1 = *(const uint32_t*)&vh[n0*72 + kt*16 + 2*c + 8];
            mma_f16(oacc[nt], pf[kt][0], pf[kt][1], pf[kt][2], pf[kt][3], b0, b1);
        }
    }

    __half* orow = out + (size_t)(win*64 + mq*16 + g) * CDIM + h*HD;
#pragma unroll
    for (int nt = 0; nt < 4; nt++) {
        __half2 o0 = __floats2half2_rn(oacc[nt][0], oacc[nt][1]);
        __half2 o1 = __floats2half2_rn(oacc[nt][2], oacc[nt][3]);
        *(__half2*)(orow + nt*8 + 2*c)          = o0;
        *(__half2*)(orow + 8*CDIM + nt*8 + 2*c) = o1;
    }
}

// ---------------------------------------------------------------------------
extern "C" void kernel_launch(void* const* d_in, const int* in_sizes, int n_in,
                              void* d_out, int out_size)
{
    const float* LH      = (const float*)d_in[0];
    const float* HL      = (const float*)d_in[1];
    const float* HH      = (const float*)d_in[2];
    const float* Spat    = (const float*)d_in[3];
    const float* w_hllh  = (const float*)d_in[4];
    const float* b_hllh  = (const float*)d_in[5];
    const float* w_hh    = (const float*)d_in[6];
    const float* b_hh    = (const float*)d_in[7];
    const float* w_spat  = (const float*)d_in[8];
    const float* b_spat  = (const float*)d_in[9];
    const float* ln1x_g  = (const float*)d_in[10];
    const float* ln1x_b  = (const float*)d_in[11];
    const float* ln1y_g  = (const float*)d_in[12];
    const float* ln1y_b  = (const float*)d_in[13];
    const float* qkv_w   = (const float*)d_in[14];
    const float* qkv_b   = (const float*)d_in[15];
    const float* qkv2_w  = (const float*)d_in[16];
    const float* qkv2_b  = (const float*)d_in[17];
    const float* qkv3_w  = (const float*)d_in[18];
    const float* qkv3_b  = (const float*)d_in[19];
    const float* proj_w  = (const float*)d_in[20];
    const float* proj_b  = (const float*)d_in[21];
    const float* rpb     = (const float*)d_in[22];
    const float* ln2_g   = (const float*)d_in[23];
    const float* ln2_b   = (const float*)d_in[24];
    const float* fc1_w   = (const float*)d_in[25];
    const float* fc1_b   = (const float*)d_in[26];
    const float* fc2_w   = (const float*)d_in[27];
    const float* fc2_b   = (const float*)d_in[28];
    float* out = (float*)d_out;

    __half *inx, *iny, *inz, *x, *y, *xn, *yn, *q, *kv, *ao, *po, *ln2h, *hbuf, *wbuf;
    float *shrt, *zt, *zt2;
    cudaGetSymbolAddress((void**)&inx,  g_inx);
    cudaGetSymbolAddress((void**)&iny,  g_iny);
    cudaGetSymbolAddress((void**)&inz,  g_inz);
    cudaGetSymbolAddress((void**)&x,    g_x);
    cudaGetSymbolAddress((void**)&y,    g_y);
    cudaGetSymbolAddress((void**)&xn,   g_xn);
    cudaGetSymbolAddress((void**)&yn,   g_yn);
    cudaGetSymbolAddress((void**)&shrt, g_short);
    cudaGetSymbolAddress((void**)&q,    g_q);
    cudaGetSymbolAddress((void**)&kv,   g_kv);
    cudaGetSymbolAddress((void**)&ao,   g_ao);
    cudaGetSymbolAddress((void**)&po,   g_po);
    cudaGetSymbolAddress((void**)&zt,   g_zt);
    cudaGetSymbolAddress((void**)&ln2h, g_ln2);
    cudaGetSymbolAddress((void**)&hbuf, g_h);
    cudaGetSymbolAddress((void**)&zt2,  g_zt2);
    cudaGetSymbolAddress((void**)&wbuf, g_w);

    static int smem_set = 0;
    if (!smem_set) {
        cudaFuncSetAttribute(gemm_h, cudaFuncAttributeMaxDynamicSharedMemorySize, GSMEM);
        smem_set = 1;
    }

    dim3 tb(32, 8);
    const int M = P_TOT;
    const float qscale = 0.17677669529663688f;

    conv_w_kernel<<<(W_TOT + 255)/256, 256>>>(w_hllh, w_hh, w_spat, qkv_w, qkv2_w,
                                              qkv3_w, proj_w, fc1_w, fc2_w, wbuf);

    pack_kernel<<<dim3(HW_/32, 2, B_), tb>>>(LH,   inx, 64, 128, 0);
    pack_kernel<<<dim3(HW_/32, 2, B_), tb>>>(HL,   inx, 64, 128, 64);
    pack_kernel<<<dim3(HW_/32, 2, B_), tb>>>(HH,   inz, 64, 64, 0);
    pack_kernel<<<dim3(HW_/32, 2, B_), tb>>>(Spat, iny, 64, 64, 0);

    gemm_h<<<dim3(2, M/128), 256, GSMEM>>>(inx, wbuf+WO_HLLH, b_hllh, nullptr, nullptr, x,    M, 256, 128, 1.f, 0, 1);
    gemm_h<<<dim3(2, M/128), 256, GSMEM>>>(inz, wbuf+WO_HH,   b_hh,   nullptr, nullptr, shrt, M, 256, 64,  1.f, 0, 0);
    gemm_h<<<dim3(2, M/128), 256, GSMEM>>>(iny, wbuf+WO_SPAT, b_spat, nullptr, nullptr, y,    M, 256, 64,  1.f, 0, 1);

    ln_part_kernel<<<M/8, 256>>>(x, ln1x_g, ln1x_b, xn, 1);
    ln_part_kernel<<<M/8, 256>>>(y, ln1y_g, ln1y_b, yn, 1);

    // q projection; fused k|v projection into kv [P,512]
    gemm_h<<<dim3(2, M/128), 256, GSMEM>>>(xn, wbuf+WO_QKV,  qkv_b,  nullptr, nullptr, q,  M, 256, 256, qscale, 0, 1);
    gemm_h<<<dim3(4, M/128), 256, GSMEM>>>(yn, wbuf+WO_QKV2, qkv2_b, qkv3_b,  nullptr, kv, M, 512, 256, 1.f, 0, 1);

    attn_kernel<<<dim3(2048, NHEAD/2), 256>>>(q, kv, rpb, ao);

    gemm_h<<<dim3(2, M/128), 256, GSMEM>>>(ao, wbuf+WO_PROJ, proj_b, nullptr, nullptr, po, M, 256, 256, 1.f, 0, 1);

    res_ln2_kernel<<<M/8, 256>>>(po, shrt, ln2_g, ln2_b, zt, ln2h);

    gemm_h<<<dim3(8, M/128), 256, GSMEM>>>(ln2h, wbuf+WO_FC1, fc1_b, nullptr, nullptr, hbuf, M, HID, 256, 1.f, 1, 1);
    gemm_h<<<dim3(2, M/128), 256, GSMEM>>>(hbuf, wbuf+WO_FC2, fc2_b, nullptr, zt,      zt2,  M, 256, HID, 1.f, 0, 0);

    unpack_kernel<<<dim3(HW_/32, 8, B_), tb>>>(zt2, out);
}

// round 12
// speedup vs baseline: 1.4809x; 1.0071x over previous
#include <cuda_runtime.h>
#include <cuda_fp16.h>
#include <math.h>
#include <stdint.h>

// ---------------------------------------------------------------------------
// WaveletSwinTransformerBlock — fp16 mma GEMMs, 3-stage pipe,
// fc2 epilogue writes NCHW fp32 directly (no unpack), fp16 shortcut.
// ---------------------------------------------------------------------------

#define B_     8
#define H_     128
#define W_     128
#define HW_    (H_*W_)           // 16384
#define P_TOT  (B_*HW_)          // 131072
#define CDIM   256
#define NHEAD  8
#define HD     32
#define HID    1024

// ------------------------- scratch buffers (static) ------------------------
__device__ __half g_inx[(size_t)P_TOT*128];
__device__ __half g_iny[(size_t)P_TOT*64];
__device__ __half g_inz[(size_t)P_TOT*64];
__device__ __half g_x    [(size_t)P_TOT*CDIM];
__device__ __half g_y    [(size_t)P_TOT*CDIM];
__device__ __half g_xn   [(size_t)P_TOT*CDIM];
__device__ __half g_yn   [(size_t)P_TOT*CDIM];
__device__ __half g_short[(size_t)P_TOT*CDIM];
__device__ __half g_q    [(size_t)P_TOT*CDIM];
__device__ __half g_kv   [(size_t)P_TOT*512];
__device__ __half g_ao   [(size_t)P_TOT*CDIM];
__device__ __half g_po   [(size_t)P_TOT*CDIM];
__device__ float  g_zt   [(size_t)P_TOT*CDIM];
__device__ __half g_ln2  [(size_t)P_TOT*CDIM];
__device__ __half g_h    [(size_t)P_TOT*HID];

// fp16 weights, concatenated
#define WO_HLLH 0
#define WO_HH   32768
#define WO_SPAT 49152
#define WO_QKV  65536
#define WO_QKV2 131072
#define WO_QKV3 196608
#define WO_PROJ 262144
#define WO_FC1  327680
#define WO_FC2  589824
#define W_TOT   851968
__device__ __half g_w[W_TOT];

__device__ __forceinline__ int win_row(int p) {
    int b  = p >> 14;
    int hw = p & 16383;
    int h  = hw >> 7, w = hw & 127;
    int win = (b << 8) | ((h >> 3) << 4) | (w >> 3);
    int tok = ((h & 7) << 3) | (w & 7);
    return (win << 6) | tok;
}

// ------------------------- weight conversion -------------------------------
__global__ void conv_w_kernel(const float* w0, const float* w1, const float* w2,
                              const float* w3, const float* w4, const float* w5,
                              const float* w6, const float* w7, const float* w8,
                              __half* dst)
{
    int i = blockIdx.x * 256 + threadIdx.x;
    if (i >= W_TOT) return;
    float v;
    if      (i < WO_HH)   v = w0[i - WO_HLLH];
    else if (i < WO_SPAT) v = w1[i - WO_HH];
    else if (i < WO_QKV)  v = w2[i - WO_SPAT];
    else if (i < WO_QKV2) v = w3[i - WO_QKV];
    else if (i < WO_QKV3) v = w4[i - WO_QKV2];
    else if (i < WO_PROJ) v = w5[i - WO_QKV3];
    else if (i < WO_FC1)  v = w6[i - WO_PROJ];
    else if (i < WO_FC2)  v = w7[i - WO_FC1];
    else                  v = w8[i - WO_FC2];
    dst[i] = __float2half_rn(v);
}

// ------------------------- pack: NCHW -> [P, Cin] fp16 ---------------------
__global__ void pack_kernel(const float* __restrict__ src, __half* __restrict__ dst,
                            int Cin, int rowStride, int colOff)
{
    __shared__ float s[32][33];
    int hw0 = blockIdx.x * 32;
    int c0  = blockIdx.y * 32;
    int b   = blockIdx.z;
    int tx = threadIdx.x, ty = threadIdx.y;
#pragma unroll
    for (int i = 0; i < 4; i++)
        s[ty + 8*i][tx] = src[((size_t)(b*Cin + c0 + ty + 8*i))*HW_ + hw0 + tx];
    __syncthreads();
#pragma unroll
    for (int i = 0; i < 4; i++)
        dst[(size_t)(b*HW_ + hw0 + ty + 8*i)*rowStride + colOff + c0 + tx] =
            __float2half_rn(s[tx][ty + 8*i]);
}

// ------------------------- fp16 tensor-core GEMM ---------------------------
// Block 128x128, k-tile 64 halfs, 8 warps (2M x 4N), 3-stage cp.async,
// one __syncthreads per k-iteration.
// out_mode: 0 = fp32 row-major, 1 = fp16 row-major, 2 = fp32 NCHW transpose.
#define HP 72
#define HSTAGE (128*HP)
#define GSMEM  (3 * 2 * HSTAGE * 2)  // 110592 bytes

__device__ __forceinline__ void mma_f16(float c[4], uint32_t a0, uint32_t a1,
                                        uint32_t a2, uint32_t a3,
                                        uint32_t b0, uint32_t b1)
{
    asm volatile(
        "mma.sync.aligned.m16n8k16.row.col.f32.f16.f16.f32 "
        "{%0,%1,%2,%3}, {%4,%5,%6,%7}, {%8,%9}, {%0,%1,%2,%3};\n"
        : "+f"(c[0]), "+f"(c[1]), "+f"(c[2]), "+f"(c[3])
        : "r"(a0), "r"(a1), "r"(a2), "r"(a3), "r"(b0), "r"(b1));
}

__device__ __forceinline__ void cp16(uint32_t dst_smem, const __half* src) {
    asm volatile("cp.async.cg.shared.global [%0], [%1], 16;\n"
                 :: "r"(dst_smem), "l"(src));
}

__global__ __launch_bounds__(256, 2)
void gemm_h(const __half* __restrict__ A, const __half* __restrict__ Wm,
            const float* __restrict__ bias, const float* __restrict__ bias2,
            const float* __restrict__ res, void* __restrict__ Cout,
            int M, int N, int K, float alpha, int gelu, int out_mode)
{
    extern __shared__ __half smem[];
    const uint32_t smem_base = (uint32_t)__cvta_generic_to_shared(smem);

    int bx = blockIdx.x, by = blockIdx.y;
    int tid  = threadIdx.x;
    int warp = tid >> 5, lane = tid & 31;
    int wm = warp >> 2;
    int wn = warp & 3;
    int g  = lane >> 2, c = lane & 3;

    const __half* Ab = A  + (size_t)by * 128 * K;
    const __half* Wb = Wm + (size_t)bx * 128 * K;

    float acc[4][4][4];
#pragma unroll
    for (int i = 0; i < 4; i++)
#pragma unroll
        for (int j = 0; j < 4; j++)
#pragma unroll
            for (int r = 0; r < 4; r++) acc[i][j][r] = 0.f;

    const int nk = K >> 6;

    auto issue = [&](int kt, int buf) {
        int k0 = kt << 6;
        uint32_t sa = smem_base + (uint32_t)(buf * 2 * HSTAGE) * 2u;
        uint32_t sb = sa + (uint32_t)HSTAGE * 2u;
#pragma unroll
        for (int i = 0; i < 4; i++) {
            int ch = tid + (i << 8);
            int row = ch >> 3;
            int c8  = (ch & 7) << 3;
            cp16(sa + (uint32_t)(row * HP + c8) * 2u, Ab + (size_t)row * K + k0 + c8);
            cp16(sb + (uint32_t)(row * HP + c8) * 2u, Wb + (size_t)row * K + k0 + c8);
        }
        asm volatile("cp.async.commit_group;\n");
    };

    issue(0, 0);
    if (nk > 1) issue(1, 1);

    for (int kt = 0; kt < nk; kt++) {
        if (kt + 1 < nk) asm volatile("cp.async.wait_group 1;\n");
        else             asm volatile("cp.async.wait_group 0;\n");
        __syncthreads();                      // also releases buf (kt+2)%3
        if (kt + 2 < nk) issue(kt + 2, (kt + 2) % 3);

        const __half* As = smem + (kt % 3) * 2 * HSTAGE;
        const __half* Bs = As + HSTAGE;
        int mrow = wm * 64;
        int ncol = wn * 32;

#pragma unroll
        for (int ks = 0; ks < 4; ks++) {
            int k0 = ks << 4;
            uint32_t af[4][4];
#pragma unroll
            for (int mt = 0; mt < 4; mt++) {
                int r0 = mrow + mt * 16 + g;
                af[mt][0] = *(const uint32_t*)&As[r0 * HP + k0 + 2*c];
                af[mt][1] = *(const uint32_t*)&As[(r0 + 8) * HP + k0 + 2*c];
                af[mt][2] = *(const uint32_t*)&As[r0 * HP + k0 + 2*c + 8];
                af[mt][3] = *(const uint32_t*)&As[(r0 + 8) * HP + k0 + 2*c + 8];
            }
            uint32_t bf[4][2];
#pragma unroll
            for (int nt = 0; nt < 4; nt++) {
                int n0 = ncol + nt * 8 + g;
                bf[nt][0] = *(const uint32_t*)&Bs[n0 * HP + k0 + 2*c];
                bf[nt][1] = *(const uint32_t*)&Bs[n0 * HP + k0 + 2*c + 8];
            }
#pragma unroll
            for (int mt = 0; mt < 4; mt++)
#pragma unroll
                for (int nt = 0; nt < 4; nt++)
                    mma_f16(acc[mt][nt], af[mt][0], af[mt][1], af[mt][2], af[mt][3],
                            bf[nt][0], bf[nt][1]);
        }
    }
    __syncthreads();

    float* Cf = (float*)Cout;
    __half* Ch = (__half*)Cout;
#pragma unroll
    for (int mt = 0; mt < 4; mt++) {
#pragma unroll
        for (int nt = 0; nt < 4; nt++) {
            int row = by * 128 + wm * 64 + mt * 16 + g;
            int col = bx * 128 + wn * 32 + nt * 8 + 2 * c;
            const float* bp = bias;
            int cadj = col;
            if (bias2 && col >= 256) { bp = bias2; cadj = col - 256; }
#pragma unroll
            for (int half_ = 0; half_ < 2; half_++) {
                int rr = row + half_ * 8;
                float v0 = (acc[mt][nt][half_*2+0] + bp[cadj])     * alpha;
                float v1 = (acc[mt][nt][half_*2+1] + bp[cadj + 1]) * alpha;
                if (gelu) {
                    v0 = 0.5f * v0 * (1.0f + erff(v0 * 0.70710678118654752f));
                    v1 = 0.5f * v1 * (1.0f + erff(v1 * 0.70710678118654752f));
                }
                if (res) {
                    v0 += res[(size_t)rr * N + col];
                    v1 += res[(size_t)rr * N + col + 1];
                }
                if (out_mode == 2) {
                    // NCHW fp32: row rr = pixel p, planes col and col+1
                    int b  = rr >> 14;
                    int hw = rr & 16383;
                    float* op = Cf + ((size_t)(b * CDIM + col)) * HW_ + hw;
                    op[0]   = v0;
                    op[HW_] = v1;
                } else if (out_mode == 1) {
                    __half2 o = __floats2half2_rn(v0, v1);
                    *(__half2*)&Ch[(size_t)rr * N + col] = o;
                } else {
                    float2 o = {v0, v1};
                    *(float2*)&Cf[(size_t)rr * N + col] = o;
                }
            }
        }
    }
}

// ------------------------- LayerNorm + window partition (fp16 in/out) ------
__global__ void ln_part_kernel(const __half* __restrict__ x, const float* __restrict__ g,
                               const float* __restrict__ b, __half* __restrict__ out,
                               int to_window)
{
    int warp = threadIdx.x >> 5, lane = threadIdx.x & 31;
    int p = blockIdx.x * 8 + warp;
    const __half* row = x + (size_t)p * CDIM;
    int c0 = lane * 8;
    uint4 w = *(const uint4*)(row + c0);
    __half2* hw = (__half2*)&w;
    float v[8];
#pragma unroll
    for (int i = 0; i < 4; i++) {
        float2 f = __half22float2(hw[i]);
        v[2*i] = f.x; v[2*i+1] = f.y;
    }
    float s = 0.f, sq = 0.f;
#pragma unroll
    for (int i = 0; i < 8; i++) { s += v[i]; sq += v[i]*v[i]; }
#pragma unroll
    for (int o = 16; o; o >>= 1) {
        s  += __shfl_xor_sync(0xffffffffu, s,  o);
        sq += __shfl_xor_sync(0xffffffffu, sq, o);
    }
    float mean = s * (1.0f/CDIM);
    float var  = sq * (1.0f/CDIM) - mean*mean;
    float rstd = rsqrtf(var + 1e-5f);
    int r = to_window ? win_row(p) : p;
    uint4 o4;
    __half2* ho = (__half2*)&o4;
#pragma unroll
    for (int i = 0; i < 4; i++)
        ho[i] = __floats2half2_rn((v[2*i]  -mean)*rstd*g[c0+2*i]   + b[c0+2*i],
                                  (v[2*i+1]-mean)*rstd*g[c0+2*i+1] + b[c0+2*i+1]);
    *(uint4*)(out + (size_t)r * CDIM + c0) = o4;
}

// ------------------------- residual + LN2 (window-reverse) -----------------
// shortcut now fp16; zt stays fp32 (residual base for final output)
__global__ void res_ln2_kernel(const __half* __restrict__ proj, const __half* __restrict__ sc,
                               const float* __restrict__ g, const float* __restrict__ b,
                               float* __restrict__ zt, __half* __restrict__ ln2)
{
    int warp = threadIdx.x >> 5, lane = threadIdx.x & 31;
    int p = blockIdx.x * 8 + warp;
    int r = win_row(p);
    int c0 = lane * 8;
    uint4 wp = *(const uint4*)(proj + (size_t)r * CDIM + c0);
    uint4 ws = *(const uint4*)(sc   + (size_t)p * CDIM + c0);
    __half2* hp2 = (__half2*)&wp;
    __half2* hs2 = (__half2*)&ws;
    float v[8];
#pragma unroll
    for (int i = 0; i < 4; i++) {
        float2 fp = __half22float2(hp2[i]);
        float2 fs = __half22float2(hs2[i]);
        v[2*i] = fp.x + fs.x; v[2*i+1] = fp.y + fs.y;
    }
    float4 z0 = {v[0],v[1],v[2],v[3]};
    float4 z1 = {v[4],v[5],v[6],v[7]};
    *(float4*)(zt + (size_t)p*CDIM + c0)     = z0;
    *(float4*)(zt + (size_t)p*CDIM + c0 + 4) = z1;
    float s = 0.f, sq = 0.f;
#pragma unroll
    for (int i = 0; i < 8; i++) { s += v[i]; sq += v[i]*v[i]; }
#pragma unroll
    for (int o = 16; o; o >>= 1) {
        s  += __shfl_xor_sync(0xffffffffu, s,  o);
        sq += __shfl_xor_sync(0xffffffffu, sq, o);
    }
    float mean = s * (1.0f/CDIM);
    float var  = sq * (1.0f/CDIM) - mean*mean;
    float rstd = rsqrtf(var + 1e-5f);
    uint4 o4;
    __half2* ho = (__half2*)&o4;
#pragma unroll
    for (int i = 0; i < 4; i++)
        ho[i] = __floats2half2_rn((v[2*i]  -mean)*rstd*g[c0+2*i]   + b[c0+2*i],
                                  (v[2*i+1]-mean)*rstd*g[c0+2*i+1] + b[c0+2*i+1]);
    *(uint4*)(ln2 + (size_t)p * CDIM + c0) = o4;
}

// ------------------------- mma windowed attention --------------------------
// q in [P,256]; k/v interleaved in kv [P,512] (k cols 0..255, v cols 256..511)
__global__ __launch_bounds__(256)
void attn_kernel(const __half* __restrict__ q, const __half* __restrict__ kv,
                 const float* __restrict__ rpb, __half* __restrict__ out)
{
    __shared__ __half qs [64*72];
    __shared__ __half ks_[64*72];
    __shared__ __half vst[2*32*72];
    __shared__ float  rpbs[1800];
    int win = blockIdx.x, hp = blockIdx.y;
    int tid = threadIdx.x;
    size_t qbase  = (size_t)win * 64 * CDIM + hp * 64;
    size_t kvbase = (size_t)win * 64 * 512  + hp * 64;

    for (int i = tid; i < 2048; i += 256) {
        int n = i >> 5, j = i & 31;
        *(uint32_t*)(qs  + n*72 + 2*j) = *(const uint32_t*)(q  + qbase  + (size_t)n*CDIM + 2*j);
        *(uint32_t*)(ks_ + n*72 + 2*j) = *(const uint32_t*)(kv + kvbase + (size_t)n*512  + 2*j);
        __half2 wv = *(const __half2*)(kv + kvbase + 256 + (size_t)n*512 + 2*j);
        int dl = 2*j, hl = dl >> 5, dd = dl & 31;
        vst[hl*2304 + dd*72 + n]     = __low2half(wv);
        vst[hl*2304 + (dd+1)*72 + n] = __high2half(wv);
    }
    for (int i = tid; i < 1800; i += 256) rpbs[i] = rpb[i];
    __syncthreads();

    int warp = tid >> 5, lane = tid & 31;
    int hl = warp >> 2, mq = warp & 3;
    int h  = hp * 2 + hl;
    int g  = lane >> 2, c = lane & 3;

    float sacc[8][4];
#pragma unroll
    for (int nt = 0; nt < 8; nt++)
#pragma unroll
        for (int r = 0; r < 4; r++) sacc[nt][r] = 0.f;

#pragma unroll
    for (int ks = 0; ks < 2; ks++) {
        int kc = hl*32 + ks*16 + 2*c;
        int r0 = mq*16 + g;
        uint32_t a0 = *(const uint32_t*)&qs[r0*72 + kc];
        uint32_t a1 = *(const uint32_t*)&qs[(r0+8)*72 + kc];
        uint32_t a2 = *(const uint32_t*)&qs[r0*72 + kc + 8];
        uint32_t a3 = *(const uint32_t*)&qs[(r0+8)*72 + kc + 8];
#pragma unroll
        for (int nt = 0; nt < 8; nt++) {
            int n0 = nt*8 + g;
            uint32_t b0 = *(const uint32_t*)&ks_[n0*72 + kc];
            uint32_t b1 = *(const uint32_t*)&ks_[n0*72 + kc + 8];
            mma_f16(sacc[nt], a0, a1, a2, a3, b0, b1);
        }
    }

    int dj0 = g - 2*c + 7, dj1 = dj0 - 1;
#pragma unroll
    for (int nt = 0; nt < 8; nt++) {
        int di0 = mq*2 - nt + 7, di1 = di0 + 1;
        sacc[nt][0] += rpbs[(di0*15 + dj0)*NHEAD + h];
        sacc[nt][1] += rpbs[(di0*15 + dj1)*NHEAD + h];
        sacc[nt][2] += rpbs[(di1*15 + dj0)*NHEAD + h];
        sacc[nt][3] += rpbs[(di1*15 + dj1)*NHEAD + h];
    }

    float mxA = -1e30f, mxB = -1e30f;
#pragma unroll
    for (int nt = 0; nt < 8; nt++) {
        mxA = fmaxf(mxA, fmaxf(sacc[nt][0], sacc[nt][1]));
        mxB = fmaxf(mxB, fmaxf(sacc[nt][2], sacc[nt][3]));
    }
#pragma unroll
    for (int o = 1; o <= 2; o <<= 1) {
        mxA = fmaxf(mxA, __shfl_xor_sync(0xffffffffu, mxA, o));
        mxB = fmaxf(mxB, __shfl_xor_sync(0xffffffffu, mxB, o));
    }
    float smA = 0.f, smB = 0.f;
#pragma unroll
    for (int nt = 0; nt < 8; nt++) {
        sacc[nt][0] = expf(sacc[nt][0] - mxA); smA += sacc[nt][0];
        sacc[nt][1] = expf(sacc[nt][1] - mxA); smA += sacc[nt][1];
        sacc[nt][2] = expf(sacc[nt][2] - mxB); smB += sacc[nt][2];
        sacc[nt][3] = expf(sacc[nt][3] - mxB); smB += sacc[nt][3];
    }
#pragma unroll
    for (int o = 1; o <= 2; o <<= 1) {
        smA += __shfl_xor_sync(0xffffffffu, smA, o);
        smB += __shfl_xor_sync(0xffffffffu, smB, o);
    }
    float ivA = 1.0f / smA, ivB = 1.0f / smB;

    uint32_t pf[4][4];
#pragma unroll
    for (int kt = 0; kt < 4; kt++) {
        __half2 t;
        t = __floats2half2_rn(sacc[2*kt][0]*ivA,   sacc[2*kt][1]*ivA);   pf[kt][0] = *(uint32_t*)&t;
        t = __floats2half2_rn(sacc[2*kt][2]*ivB,   sacc[2*kt][3]*ivB);   pf[kt][1] = *(uint32_t*)&t;
        t = __floats2half2_rn(sacc[2*kt+1][0]*ivA, sacc[2*kt+1][1]*ivA); pf[kt][2] = *(uint32_t*)&t;
        t = __floats2half2_rn(sacc[2*kt+1][2]*ivB, sacc[2*kt+1][3]*ivB); pf[kt][3] = *(uint32_t*)&t;
    }

    float oacc[4][4];
#pragma unroll
    for (int nt = 0; nt < 4; nt++)
#pragma unroll
        for (int r = 0; r < 4; r++) oacc[nt][r] = 0.f;
    const __half* vh = vst + hl*2304;
#pragma unroll
    for (int kt = 0; kt < 4; kt++) {
#pragma unroll
        for (int nt = 0; nt < 4; nt++) {
            int n0 = nt*8 + g;
            uint32_t b0 = *(const uint32_t*)&vh[n0*72 + kt*16 + 2*c];
            uint32_t b1 = *(const uint32_t*)&vh[n0*72 + kt*16 + 2*c + 8];
            mma_f16(oacc[nt], pf[kt][0], pf[kt][1], pf[kt][2], pf[kt][3], b0, b1);
        }
    }

    __half* orow = out + (size_t)(win*64 + mq*16 + g) * CDIM + h*HD;
#pragma unroll
    for (int nt = 0; nt < 4; nt++) {
        __half2 o0 = __floats2half2_rn(oacc[nt][0], oacc[nt][1]);
        __half2 o1 = __floats2half2_rn(oacc[nt][2], oacc[nt][3]);
        *(__half2*)(orow + nt*8 + 2*c)          = o0;
        *(__half2*)(orow + 8*CDIM + nt*8 + 2*c) = o1;
    }
}

// ---------------------------------------------------------------------------
extern "C" void kernel_launch(void* const* d_in, const int* in_sizes, int n_in,
                              void* d_out, int out_size)
{
    const float* LH      = (const float*)d_in[0];
    const float* HL      = (const float*)d_in[1];
    const float* HH      = (const float*)d_in[2];
    const float* Spat    = (const float*)d_in[3];
    const float* w_hllh  = (const float*)d_in[4];
    const float* b_hllh  = (const float*)d_in[5];
    const float* w_hh    = (const float*)d_in[6];
    const float* b_hh    = (const float*)d_in[7];
    const float* w_spat  = (const float*)d_in[8];
    const float* b_spat  = (const float*)d_in[9];
    const float* ln1x_g  = (const float*)d_in[10];
    const float* ln1x_b  = (const float*)d_in[11];
    const float* ln1y_g  = (const float*)d_in[12];
    const float* ln1y_b  = (const float*)d_in[13];
    const float* qkv_w   = (const float*)d_in[14];
    const float* qkv_b   = (const float*)d_in[15];
    const float* qkv2_w  = (const float*)d_in[16];
    const float* qkv2_b  = (const float*)d_in[17];
    const float* qkv3_w  = (const float*)d_in[18];
    const float* qkv3_b  = (const float*)d_in[19];
    const float* proj_w  = (const float*)d_in[20];
    const float* proj_b  = (const float*)d_in[21];
    const float* rpb     = (const float*)d_in[22];
    const float* ln2_g   = (const float*)d_in[23];
    const float* ln2_b   = (const float*)d_in[24];
    const float* fc1_w   = (const float*)d_in[25];
    const float* fc1_b   = (const float*)d_in[26];
    const float* fc2_w   = (const float*)d_in[27];
    const float* fc2_b   = (const float*)d_in[28];
    float* out = (float*)d_out;

    __half *inx, *iny, *inz, *x, *y, *xn, *yn, *shrt, *q, *kv, *ao, *po, *ln2h, *hbuf, *wbuf;
    float *zt;
    cudaGetSymbolAddress((void**)&inx,  g_inx);
    cudaGetSymbolAddress((void**)&iny,  g_iny);
    cudaGetSymbolAddress((void**)&inz,  g_inz);
    cudaGetSymbolAddress((void**)&x,    g_x);
    cudaGetSymbolAddress((void**)&y,    g_y);
    cudaGetSymbolAddress((void**)&xn,   g_xn);
    cudaGetSymbolAddress((void**)&yn,   g_yn);
    cudaGetSymbolAddress((void**)&shrt, g_short);
    cudaGetSymbolAddress((void**)&q,    g_q);
    cudaGetSymbolAddress((void**)&kv,   g_kv);
    cudaGetSymbolAddress((void**)&ao,   g_ao);
    cudaGetSymbolAddress((void**)&po,   g_po);
    cudaGetSymbolAddress((void**)&zt,   g_zt);
    cudaGetSymbolAddress((void**)&ln2h, g_ln2);
    cudaGetSymbolAddress((void**)&hbuf, g_h);
    cudaGetSymbolAddress((void**)&wbuf, g_w);

    static int smem_set = 0;
    if (!smem_set) {
        cudaFuncSetAttribute(gemm_h, cudaFuncAttributeMaxDynamicSharedMemorySize, GSMEM);
        smem_set = 1;
    }

    dim3 tb(32, 8);
    const int M = P_TOT;
    const float qscale = 0.17677669529663688f;

    conv_w_kernel<<<(W_TOT + 255)/256, 256>>>(w_hllh, w_hh, w_spat, qkv_w, qkv2_w,
                                              qkv3_w, proj_w, fc1_w, fc2_w, wbuf);

    pack_kernel<<<dim3(HW_/32, 2, B_), tb>>>(LH,   inx, 64, 128, 0);
    pack_kernel<<<dim3(HW_/32, 2, B_), tb>>>(HL,   inx, 64, 128, 64);
    pack_kernel<<<dim3(HW_/32, 2, B_), tb>>>(HH,   inz, 64, 64, 0);
    pack_kernel<<<dim3(HW_/32, 2, B_), tb>>>(Spat, iny, 64, 64, 0);

    // 1x1 convs (x, y, shortcut all fp16 now)
    gemm_h<<<dim3(2, M/128), 256, GSMEM>>>(inx, wbuf+WO_HLLH, b_hllh, nullptr, nullptr, x,    M, 256, 128, 1.f, 0, 1);
    gemm_h<<<dim3(2, M/128), 256, GSMEM>>>(inz, wbuf+WO_HH,   b_hh,   nullptr, nullptr, shrt, M, 256, 64,  1.f, 0, 1);
    gemm_h<<<dim3(2, M/128), 256, GSMEM>>>(iny, wbuf+WO_SPAT, b_spat, nullptr, nullptr, y,    M, 256, 64,  1.f, 0, 1);

    ln_part_kernel<<<M/8, 256>>>(x, ln1x_g, ln1x_b, xn, 1);
    ln_part_kernel<<<M/8, 256>>>(y, ln1y_g, ln1y_b, yn, 1);

    // q projection; fused k|v projection into kv [P,512]
    gemm_h<<<dim3(2, M/128), 256, GSMEM>>>(xn, wbuf+WO_QKV,  qkv_b,  nullptr, nullptr, q,  M, 256, 256, qscale, 0, 1);
    gemm_h<<<dim3(4, M/128), 256, GSMEM>>>(yn, wbuf+WO_QKV2, qkv2_b, qkv3_b,  nullptr, kv, M, 512, 256, 1.f, 0, 1);

    attn_kernel<<<dim3(2048, NHEAD/2), 256>>>(q, kv, rpb, ao);

    gemm_h<<<dim3(2, M/128), 256, GSMEM>>>(ao, wbuf+WO_PROJ, proj_b, nullptr, nullptr, po, M, 256, 256, 1.f, 0, 1);

    res_ln2_kernel<<<M/8, 256>>>(po, shrt, ln2_g, ln2_b, zt, ln2h);

    // MLP: fc1 (fp16 + gelu), fc2 writes final fp32 NCHW directly (+ zt residual)
    gemm_h<<<dim3(8, M/128), 256, GSMEM>>>(ln2h, wbuf+WO_FC1, fc1_b, nullptr, nullptr, hbuf, M, HID, 256, 1.f, 1, 1);
    gemm_h<<<dim3(2, M/128), 256, GSMEM>>>(hbuf, wbuf+WO_FC2, fc2_b, nullptr, zt,      out,  M, 256, HID, 1.f, 0, 2);
}

// round 13
// speedup vs baseline: 1.5940x; 1.0764x over previous
#include <cuda_runtime.h>
#include <cuda_fp16.h>
#include <math.h>
#include <stdint.h>

// ---------------------------------------------------------------------------
// WaveletSwinTransformerBlock — fp16 mma GEMMs, 3-stage pipe, ldmatrix frags,
// fc2 epilogue writes NCHW fp32 directly, fp16 shortcut.
// ---------------------------------------------------------------------------

#define B_     8
#define H_     128
#define W_     128
#define HW_    (H_*W_)           // 16384
#define P_TOT  (B_*HW_)          // 131072
#define CDIM   256
#define NHEAD  8
#define HD     32
#define HID    1024

// ------------------------- scratch buffers (static) ------------------------
__device__ __half g_inx[(size_t)P_TOT*128];
__device__ __half g_iny[(size_t)P_TOT*64];
__device__ __half g_inz[(size_t)P_TOT*64];
__device__ __half g_x    [(size_t)P_TOT*CDIM];
__device__ __half g_y    [(size_t)P_TOT*CDIM];
__device__ __half g_xn   [(size_t)P_TOT*CDIM];
__device__ __half g_yn   [(size_t)P_TOT*CDIM];
__device__ __half g_short[(size_t)P_TOT*CDIM];
__device__ __half g_q    [(size_t)P_TOT*CDIM];
__device__ __half g_kv   [(size_t)P_TOT*512];
__device__ __half g_ao   [(size_t)P_TOT*CDIM];
__device__ __half g_po   [(size_t)P_TOT*CDIM];
__device__ float  g_zt   [(size_t)P_TOT*CDIM];
__device__ __half g_ln2  [(size_t)P_TOT*CDIM];
__device__ __half g_h    [(size_t)P_TOT*HID];

// fp16 weights, concatenated
#define WO_HLLH 0
#define WO_HH   32768
#define WO_SPAT 49152
#define WO_QKV  65536
#define WO_QKV2 131072
#define WO_QKV3 196608
#define WO_PROJ 262144
#define WO_FC1  327680
#define WO_FC2  589824
#define W_TOT   851968
__device__ __half g_w[W_TOT];

__device__ __forceinline__ int win_row(int p) {
    int b  = p >> 14;
    int hw = p & 16383;
    int h  = hw >> 7, w = hw & 127;
    int win = (b << 8) | ((h >> 3) << 4) | (w >> 3);
    int tok = ((h & 7) << 3) | (w & 7);
    return (win << 6) | tok;
}

// ------------------------- weight conversion -------------------------------
__global__ void conv_w_kernel(const float* w0, const float* w1, const float* w2,
                              const float* w3, const float* w4, const float* w5,
                              const float* w6, const float* w7, const float* w8,
                              __half* dst)
{
    int i = blockIdx.x * 256 + threadIdx.x;
    if (i >= W_TOT) return;
    float v;
    if      (i < WO_HH)   v = w0[i - WO_HLLH];
    else if (i < WO_SPAT) v = w1[i - WO_HH];
    else if (i < WO_QKV)  v = w2[i - WO_SPAT];
    else if (i < WO_QKV2) v = w3[i - WO_QKV];
    else if (i < WO_QKV3) v = w4[i - WO_QKV2];
    else if (i < WO_PROJ) v = w5[i - WO_QKV3];
    else if (i < WO_FC1)  v = w6[i - WO_PROJ];
    else if (i < WO_FC2)  v = w7[i - WO_FC1];
    else                  v = w8[i - WO_FC2];
    dst[i] = __float2half_rn(v);
}

// ------------------------- pack: NCHW -> [P, Cin] fp16 ---------------------
__global__ void pack_kernel(const float* __restrict__ src, __half* __restrict__ dst,
                            int Cin, int rowStride, int colOff)
{
    __shared__ float s[32][33];
    int hw0 = blockIdx.x * 32;
    int c0  = blockIdx.y * 32;
    int b   = blockIdx.z;
    int tx = threadIdx.x, ty = threadIdx.y;
#pragma unroll
    for (int i = 0; i < 4; i++)
        s[ty + 8*i][tx] = src[((size_t)(b*Cin + c0 + ty + 8*i))*HW_ + hw0 + tx];
    __syncthreads();
#pragma unroll
    for (int i = 0; i < 4; i++)
        dst[(size_t)(b*HW_ + hw0 + ty + 8*i)*rowStride + colOff + c0 + tx] =
            __float2half_rn(s[tx][ty + 8*i]);
}

// ------------------------- fp16 tensor-core GEMM ---------------------------
// Block 128x128, k-tile 64 halfs, 8 warps (2M x 4N), 3-stage cp.async,
// one __syncthreads per k-iteration, ldmatrix fragment loads.
// out_mode: 0 = fp32 row-major, 1 = fp16 row-major, 2 = fp32 NCHW transpose.
#define HP 72
#define HSTAGE (128*HP)
#define GSMEM  (3 * 2 * HSTAGE * 2)  // 110592 bytes

__device__ __forceinline__ void mma_f16(float c[4], uint32_t a0, uint32_t a1,
                                        uint32_t a2, uint32_t a3,
                                        uint32_t b0, uint32_t b1)
{
    asm volatile(
        "mma.sync.aligned.m16n8k16.row.col.f32.f16.f16.f32 "
        "{%0,%1,%2,%3}, {%4,%5,%6,%7}, {%8,%9}, {%0,%1,%2,%3};\n"
        : "+f"(c[0]), "+f"(c[1]), "+f"(c[2]), "+f"(c[3])
        : "r"(a0), "r"(a1), "r"(a2), "r"(a3), "r"(b0), "r"(b1));
}

__device__ __forceinline__ void ldsm4(uint32_t& r0, uint32_t& r1,
                                      uint32_t& r2, uint32_t& r3, uint32_t addr)
{
    asm volatile("ldmatrix.sync.aligned.m8n8.x4.shared.b16 {%0,%1,%2,%3}, [%4];"
                 : "=r"(r0), "=r"(r1), "=r"(r2), "=r"(r3) : "r"(addr));
}

__device__ __forceinline__ void cp16(uint32_t dst_smem, const __half* src) {
    asm volatile("cp.async.cg.shared.global [%0], [%1], 16;\n"
                 :: "r"(dst_smem), "l"(src));
}

__global__ __launch_bounds__(256, 2)
void gemm_h(const __half* __restrict__ A, const __half* __restrict__ Wm,
            const float* __restrict__ bias, const float* __restrict__ bias2,
            const float* __restrict__ res, void* __restrict__ Cout,
            int M, int N, int K, float alpha, int gelu, int out_mode)
{
    extern __shared__ __half smem[];
    const uint32_t smem_base = (uint32_t)__cvta_generic_to_shared(smem);

    int bx = blockIdx.x, by = blockIdx.y;
    int tid  = threadIdx.x;
    int warp = tid >> 5, lane = tid & 31;
    int wm = warp >> 2;
    int wn = warp & 3;
    int g  = lane >> 2, c = lane & 3;

    const __half* Ab = A  + (size_t)by * 128 * K;
    const __half* Wb = Wm + (size_t)bx * 128 * K;

    float acc[4][4][4];
#pragma unroll
    for (int i = 0; i < 4; i++)
#pragma unroll
        for (int j = 0; j < 4; j++)
#pragma unroll
            for (int r = 0; r < 4; r++) acc[i][j][r] = 0.f;

    const int nk = K >> 6;
    int mrow = wm * 64;
    int ncol = wn * 32;

    // ldmatrix lane geometry (validated in R6: rel_err bit-identical)
    int lr   = lane & 7;
    int aRow = mrow + lr + ((lane >> 3) & 1) * 8;   // + mt*16
    int aCol = (lane >> 4) << 3;                    // + k0
    int bRow = ncol + lr + ((lane >> 4) << 3);      // + ntp*16
    int bCol = ((lane >> 3) & 1) << 3;              // + k0

    auto issue = [&](int kt, int buf) {
        int k0 = kt << 6;
        uint32_t sa = smem_base + (uint32_t)(buf * 2 * HSTAGE) * 2u;
        uint32_t sb = sa + (uint32_t)HSTAGE * 2u;
#pragma unroll
        for (int i = 0; i < 4; i++) {
            int ch = tid + (i << 8);
            int row = ch >> 3;
            int c8  = (ch & 7) << 3;
            cp16(sa + (uint32_t)(row * HP + c8) * 2u, Ab + (size_t)row * K + k0 + c8);
            cp16(sb + (uint32_t)(row * HP + c8) * 2u, Wb + (size_t)row * K + k0 + c8);
        }
        asm volatile("cp.async.commit_group;\n");
    };

    issue(0, 0);
    if (nk > 1) issue(1, 1);

    for (int kt = 0; kt < nk; kt++) {
        if (kt + 1 < nk) asm volatile("cp.async.wait_group 1;\n");
        else             asm volatile("cp.async.wait_group 0;\n");
        __syncthreads();                      // also releases buf (kt+2)%3
        if (kt + 2 < nk) issue(kt + 2, (kt + 2) % 3);

        uint32_t aBase = smem_base + (uint32_t)((kt % 3) * 2 * HSTAGE) * 2u;
        uint32_t bBase = aBase + (uint32_t)HSTAGE * 2u;

#pragma unroll
        for (int ks = 0; ks < 4; ks++) {
            int k0 = ks << 4;
            uint32_t af[4][4];
#pragma unroll
            for (int mt = 0; mt < 4; mt++)
                ldsm4(af[mt][0], af[mt][1], af[mt][2], af[mt][3],
                      aBase + (uint32_t)((aRow + mt * 16) * HP + k0 + aCol) * 2u);
            uint32_t bf[4][2];
#pragma unroll
            for (int ntp = 0; ntp < 2; ntp++)
                ldsm4(bf[2*ntp][0], bf[2*ntp][1], bf[2*ntp+1][0], bf[2*ntp+1][1],
                      bBase + (uint32_t)((bRow + ntp * 16) * HP + k0 + bCol) * 2u);
#pragma unroll
            for (int mt = 0; mt < 4; mt++)
#pragma unroll
                for (int nt = 0; nt < 4; nt++)
                    mma_f16(acc[mt][nt], af[mt][0], af[mt][1], af[mt][2], af[mt][3],
                            bf[nt][0], bf[nt][1]);
        }
    }
    __syncthreads();

    float* Cf = (float*)Cout;
    __half* Ch = (__half*)Cout;
#pragma unroll
    for (int mt = 0; mt < 4; mt++) {
#pragma unroll
        for (int nt = 0; nt < 4; nt++) {
            int row = by * 128 + wm * 64 + mt * 16 + g;
            int col = bx * 128 + wn * 32 + nt * 8 + 2 * c;
            const float* bp = bias;
            int cadj = col;
            if (bias2 && col >= 256) { bp = bias2; cadj = col - 256; }
#pragma unroll
            for (int half_ = 0; half_ < 2; half_++) {
                int rr = row + half_ * 8;
                float v0 = (acc[mt][nt][half_*2+0] + bp[cadj])     * alpha;
                float v1 = (acc[mt][nt][half_*2+1] + bp[cadj + 1]) * alpha;
                if (gelu) {
                    v0 = 0.5f * v0 * (1.0f + erff(v0 * 0.70710678118654752f));
                    v1 = 0.5f * v1 * (1.0f + erff(v1 * 0.70710678118654752f));
                }
                if (res) {
                    v0 += res[(size_t)rr * N + col];
                    v1 += res[(size_t)rr * N + col + 1];
                }
                if (out_mode == 2) {
                    int b  = rr >> 14;
                    int hw = rr & 16383;
                    float* op = Cf + ((size_t)(b * CDIM + col)) * HW_ + hw;
                    op[0]   = v0;
                    op[HW_] = v1;
                } else if (out_mode == 1) {
                    __half2 o = __floats2half2_rn(v0, v1);
                    *(__half2*)&Ch[(size_t)rr * N + col] = o;
                } else {
                    float2 o = {v0, v1};
                    *(float2*)&Cf[(size_t)rr * N + col] = o;
                }
            }
        }
    }
}

// ------------------------- LayerNorm + window partition (fp16 in/out) ------
__global__ void ln_part_kernel(const __half* __restrict__ x, const float* __restrict__ g,
                               const float* __restrict__ b, __half* __restrict__ out,
                               int to_window)
{
    int warp = threadIdx.x >> 5, lane = threadIdx.x & 31;
    int p = blockIdx.x * 8 + warp;
    const __half* row = x + (size_t)p * CDIM;
    int c0 = lane * 8;
    uint4 w = *(const uint4*)(row + c0);
    __half2* hw = (__half2*)&w;
    float v[8];
#pragma unroll
    for (int i = 0; i < 4; i++) {
        float2 f = __half22float2(hw[i]);
        v[2*i] = f.x; v[2*i+1] = f.y;
    }
    float s = 0.f, sq = 0.f;
#pragma unroll
    for (int i = 0; i < 8; i++) { s += v[i]; sq += v[i]*v[i]; }
#pragma unroll
    for (int o = 16; o; o >>= 1) {
        s  += __shfl_xor_sync(0xffffffffu, s,  o);
        sq += __shfl_xor_sync(0xffffffffu, sq, o);
    }
    float mean = s * (1.0f/CDIM);
    float var  = sq * (1.0f/CDIM) - mean*mean;
    float rstd = rsqrtf(var + 1e-5f);
    int r = to_window ? win_row(p) : p;
    uint4 o4;
    __half2* ho = (__half2*)&o4;
#pragma unroll
    for (int i = 0; i < 4; i++)
        ho[i] = __floats2half2_rn((v[2*i]  -mean)*rstd*g[c0+2*i]   + b[c0+2*i],
                                  (v[2*i+1]-mean)*rstd*g[c0+2*i+1] + b[c0+2*i+1]);
    *(uint4*)(out + (size_t)r * CDIM + c0) = o4;
}

// ------------------------- residual + LN2 (window-reverse) -----------------
__global__ void res_ln2_kernel(const __half* __restrict__ proj, const __half* __restrict__ sc,
                               const float* __restrict__ g, const float* __restrict__ b,
                               float* __restrict__ zt, __half* __restrict__ ln2)
{
    int warp = threadIdx.x >> 5, lane = threadIdx.x & 31;
    int p = blockIdx.x * 8 + warp;
    int r = win_row(p);
    int c0 = lane * 8;
    uint4 wp = *(const uint4*)(proj + (size_t)r * CDIM + c0);
    uint4 ws = *(const uint4*)(sc   + (size_t)p * CDIM + c0);
    __half2* hp2 = (__half2*)&wp;
    __half2* hs2 = (__half2*)&ws;
    float v[8];
#pragma unroll
    for (int i = 0; i < 4; i++) {
        float2 fp = __half22float2(hp2[i]);
        float2 fs = __half22float2(hs2[i]);
        v[2*i] = fp.x + fs.x; v[2*i+1] = fp.y + fs.y;
    }
    float4 z0 = {v[0],v[1],v[2],v[3]};
    float4 z1 = {v[4],v[5],v[6],v[7]};
    *(float4*)(zt + (size_t)p*CDIM + c0)     = z0;
    *(float4*)(zt + (size_t)p*CDIM + c0 + 4) = z1;
    float s = 0.f, sq = 0.f;
#pragma unroll
    for (int i = 0; i < 8; i++) { s += v[i]; sq += v[i]*v[i]; }
#pragma unroll
    for (int o = 16; o; o >>= 1) {
        s  += __shfl_xor_sync(0xffffffffu, s,  o);
        sq += __shfl_xor_sync(0xffffffffu, sq, o);
    }
    float mean = s * (1.0f/CDIM);
    float var  = sq * (1.0f/CDIM) - mean*mean;
    float rstd = rsqrtf(var + 1e-5f);
    uint4 o4;
    __half2* ho = (__half2*)&o4;
#pragma unroll
    for (int i = 0; i < 4; i++)
        ho[i] = __floats2half2_rn((v[2*i]  -mean)*rstd*g[c0+2*i]   + b[c0+2*i],
                                  (v[2*i+1]-mean)*rstd*g[c0+2*i+1] + b[c0+2*i+1]);
    *(uint4*)(ln2 + (size_t)p * CDIM + c0) = o4;
}

// ------------------------- mma windowed attention --------------------------
// q in [P,256]; k/v interleaved in kv [P,512] (k cols 0..255, v cols 256..511)
__global__ __launch_bounds__(256)
void attn_kernel(const __half* __restrict__ q, const __half* __restrict__ kv,
                 const float* __restrict__ rpb, __half* __restrict__ out)
{
    __shared__ __half qs [64*72];
    __shared__ __half ks_[64*72];
    __shared__ __half vst[2*32*72];
    __shared__ float  rpbs[1800];
    int win = blockIdx.x, hp = blockIdx.y;
    int tid = threadIdx.x;
    size_t qbase  = (size_t)win * 64 * CDIM + hp * 64;
    size_t kvbase = (size_t)win * 64 * 512  + hp * 64;

    for (int i = tid; i < 2048; i += 256) {
        int n = i >> 5, j = i & 31;
        *(uint32_t*)(qs  + n*72 + 2*j) = *(const uint32_t*)(q  + qbase  + (size_t)n*CDIM + 2*j);
        *(uint32_t*)(ks_ + n*72 + 2*j) = *(const uint32_t*)(kv + kvbase + (size_t)n*512  + 2*j);
        __half2 wv = *(const __half2*)(kv + kvbase + 256 + (size_t)n*512 + 2*j);
        int dl = 2*j, hl = dl >> 5, dd = dl & 31;
        vst[hl*2304 + dd*72 + n]     = __low2half(wv);
        vst[hl*2304 + (dd+1)*72 + n] = __high2half(wv);
    }
    for (int i = tid; i < 1800; i += 256) rpbs[i] = rpb[i];
    __syncthreads();

    int warp = tid >> 5, lane = tid & 31;
    int hl = warp >> 2, mq = warp & 3;
    int h  = hp * 2 + hl;
    int g  = lane >> 2, c = lane & 3;

    float sacc[8][4];
#pragma unroll
    for (int nt = 0; nt < 8; nt++)
#pragma unroll
        for (int r = 0; r < 4; r++) sacc[nt][r] = 0.f;

#pragma unroll
    for (int ks = 0; ks < 2; ks++) {
        int kc = hl*32 + ks*16 + 2*c;
        int r0 = mq*16 + g;
        uint32_t a0 = *(const uint32_t*)&qs[r0*72 + kc];
        uint32_t a1 = *(const uint32_t*)&qs[(r0+8)*72 + kc];
        uint32_t a2 = *(const uint32_t*)&qs[r0*72 + kc + 8];
        uint32_t a3 = *(const uint32_t*)&qs[(r0+8)*72 + kc + 8];
#pragma unroll
        for (int nt = 0; nt < 8; nt++) {
            int n0 = nt*8 + g;
            uint32_t b0 = *(const uint32_t*)&ks_[n0*72 + kc];
            uint32_t b1 = *(const uint32_t*)&ks_[n0*72 + kc + 8];
            mma_f16(sacc[nt], a0, a1, a2, a3, b0, b1);
        }
    }

    int dj0 = g - 2*c + 7, dj1 = dj0 - 1;
#pragma unroll
    for (int nt = 0; nt < 8; nt++) {
        int di0 = mq*2 - nt + 7, di1 = di0 + 1;
        sacc[nt][0] += rpbs[(di0*15 + dj0)*NHEAD + h];
        sacc[nt][1] += rpbs[(di0*15 + dj1)*NHEAD + h];
        sacc[nt][2] += rpbs[(di1*15 + dj0)*NHEAD + h];
        sacc[nt][3] += rpbs[(di1*15 + dj1)*NHEAD + h];
    }

    float mxA = -1e30f, mxB = -1e30f;
#pragma unroll
    for (int nt = 0; nt < 8; nt++) {
        mxA = fmaxf(mxA, fmaxf(sacc[nt][0], sacc[nt][1]));
        mxB = fmaxf(mxB, fmaxf(sacc[nt][2], sacc[nt][3]));
    }
#pragma unroll
    for (int o = 1; o <= 2; o <<= 1) {
        mxA = fmaxf(mxA, __shfl_xor_sync(0xffffffffu, mxA, o));
        mxB = fmaxf(mxB, __shfl_xor_sync(0xffffffffu, mxB, o));
    }
    float smA = 0.f, smB = 0.f;
#pragma unroll
    for (int nt = 0; nt < 8; nt++) {
        sacc[nt][0] = expf(sacc[nt][0] - mxA); smA += sacc[nt][0];
        sacc[nt][1] = expf(sacc[nt][1] - mxA); smA += sacc[nt][1];
        sacc[nt][2] = expf(sacc[nt][2] - mxB); smB += sacc[nt][2];
        sacc[nt][3] = expf(sacc[nt][3] - mxB); smB += sacc[nt][3];
    }
#pragma unroll
    for (int o = 1; o <= 2; o <<= 1) {
        smA += __shfl_xor_sync(0xffffffffu, smA, o);
        smB += __shfl_xor_sync(0xffffffffu, smB, o);
    }
    float ivA = 1.0f / smA, ivB = 1.0f / smB;

    uint32_t pf[4][4];
#pragma unroll
    for (int kt = 0; kt < 4; kt++) {
        __half2 t;
        t = __floats2half2_rn(sacc[2*kt][0]*ivA,   sacc[2*kt][1]*ivA);   pf[kt][0] = *(uint32_t*)&t;
        t = __floats2half2_rn(sacc[2*kt][2]*ivB,   sacc[2*kt][3]*ivB);   pf[kt][1] = *(uint32_t*)&t;
        t = __floats2half2_rn(sacc[2*kt+1][0]*ivA, sacc[2*kt+1][1]*ivA); pf[kt][2] = *(uint32_t*)&t;
        t = __floats2half2_rn(sacc[2*kt+1][2]*ivB, sacc[2*kt+1][3]*ivB); pf[kt][3] = *(uint32_t*)&t;
    }

    float oacc[4][4];
#pragma unroll
    for (int nt = 0; nt < 4; nt++)
#pragma unroll
        for (int r = 0; r < 4; r++) oacc[nt][r] = 0.f;
    const __half* vh = vst + hl*2304;
#pragma unroll
    for (int kt = 0; kt < 4; kt++) {
#pragma unroll
        for (int nt = 0; nt < 4; nt++) {
            int n0 = nt*8 + g;
            uint32_t b0 = *(const uint32_t*)&vh[n0*72 + kt*16 + 2*c];
            uint32_t b1 = *(const uint32_t*)&vh[n0*72 + kt*16 + 2*c + 8];
            mma_f16(oacc[nt], pf[kt][0], pf[kt][1], pf[kt][2], pf[kt][3], b0, b1);
        }
    }

    __half* orow = out + (size_t)(win*64 + mq*16 + g) * CDIM + h*HD;
#pragma unroll
    for (int nt = 0; nt < 4; nt++) {
        __half2 o0 = __floats2half2_rn(oacc[nt][0], oacc[nt][1]);
        __half2 o1 = __floats2half2_rn(oacc[nt][2], oacc[nt][3]);
        *(__half2*)(orow + nt*8 + 2*c)          = o0;
        *(__half2*)(orow + 8*CDIM + nt*8 + 2*c) = o1;
    }
}

// ---------------------------------------------------------------------------
extern "C" void kernel_launch(void* const* d_in, const int* in_sizes, int n_in,
                              void* d_out, int out_size)
{
    const float* LH      = (const float*)d_in[0];
    const float* HL      = (const float*)d_in[1];
    const float* HH      = (const float*)d_in[2];
    const float* Spat    = (const float*)d_in[3];
    const float* w_hllh  = (const float*)d_in[4];
    const float* b_hllh  = (const float*)d_in[5];
    const float* w_hh    = (const float*)d_in[6];
    const float* b_hh    = (const float*)d_in[7];
    const float* w_spat  = (const float*)d_in[8];
    const float* b_spat  = (const float*)d_in[9];
    const float* ln1x_g  = (const float*)d_in[10];
    const float* ln1x_b  = (const float*)d_in[11];
    const float* ln1y_g  = (const float*)d_in[12];
    const float* ln1y_b  = (const float*)d_in[13];
    const float* qkv_w   = (const float*)d_in[14];
    const float* qkv_b   = (const float*)d_in[15];
    const float* qkv2_w  = (const float*)d_in[16];
    const float* qkv2_b  = (const float*)d_in[17];
    const float* qkv3_w  = (const float*)d_in[18];
    const float* qkv3_b  = (const float*)d_in[19];
    const float* proj_w  = (const float*)d_in[20];
    const float* proj_b  = (const float*)d_in[21];
    const float* rpb     = (const float*)d_in[22];
    const float* ln2_g   = (const float*)d_in[23];
    const float* ln2_b   = (const float*)d_in[24];
    const float* fc1_w   = (const float*)d_in[25];
    const float* fc1_b   = (const float*)d_in[26];
    const float* fc2_w   = (const float*)d_in[27];
    const float* fc2_b   = (const float*)d_in[28];
    float* out = (float*)d_out;

    __half *inx, *iny, *inz, *x, *y, *xn, *yn, *shrt, *q, *kv, *ao, *po, *ln2h, *hbuf, *wbuf;
    float *zt;
    cudaGetSymbolAddress((void**)&inx,  g_inx);
    cudaGetSymbolAddress((void**)&iny,  g_iny);
    cudaGetSymbolAddress((void**)&inz,  g_inz);
    cudaGetSymbolAddress((void**)&x,    g_x);
    cudaGetSymbolAddress((void**)&y,    g_y);
    cudaGetSymbolAddress((void**)&xn,   g_xn);
    cudaGetSymbolAddress((void**)&yn,   g_yn);
    cudaGetSymbolAddress((void**)&shrt, g_short);
    cudaGetSymbolAddress((void**)&q,    g_q);
    cudaGetSymbolAddress((void**)&kv,   g_kv);
    cudaGetSymbolAddress((void**)&ao,   g_ao);
    cudaGetSymbolAddress((void**)&po,   g_po);
    cudaGetSymbolAddress((void**)&zt,   g_zt);
    cudaGetSymbolAddress((void**)&ln2h, g_ln2);
    cudaGetSymbolAddress((void**)&hbuf, g_h);
    cudaGetSymbolAddress((void**)&wbuf, g_w);

    static int smem_set = 0;
    if (!smem_set) {
        cudaFuncSetAttribute(gemm_h, cudaFuncAttributeMaxDynamicSharedMemorySize, GSMEM);
        smem_set = 1;
    }

    dim3 tb(32, 8);
    const int M = P_TOT;
    const float qscale = 0.17677669529663688f;

    conv_w_kernel<<<(W_TOT + 255)/256, 256>>>(w_hllh, w_hh, w_spat, qkv_w, qkv2_w,
                                              qkv3_w, proj_w, fc1_w, fc2_w, wbuf);

    pack_kernel<<<dim3(HW_/32, 2, B_), tb>>>(LH,   inx, 64, 128, 0);
    pack_kernel<<<dim3(HW_/32, 2, B_), tb>>>(HL,   inx, 64, 128, 64);
    pack_kernel<<<dim3(HW_/32, 2, B_), tb>>>(HH,   inz, 64, 64, 0);
    pack_kernel<<<dim3(HW_/32, 2, B_), tb>>>(Spat, iny, 64, 64, 0);

    gemm_h<<<dim3(2, M/128), 256, GSMEM>>>(inx, wbuf+WO_HLLH, b_hllh, nullptr, nullptr, x,    M, 256, 128, 1.f, 0, 1);
    gemm_h<<<dim3(2, M/128), 256, GSMEM>>>(inz, wbuf+WO_HH,   b_hh,   nullptr, nullptr, shrt, M, 256, 64,  1.f, 0, 1);
    gemm_h<<<dim3(2, M/128), 256, GSMEM>>>(iny, wbuf+WO_SPAT, b_spat, nullptr, nullptr, y,    M, 256, 64,  1.f, 0, 1);

    ln_part_kernel<<<M/8, 256>>>(x, ln1x_g, ln1x_b, xn, 1);
    ln_part_kernel<<<M/8, 256>>>(y, ln1y_g, ln1y_b, yn, 1);

    gemm_h<<<dim3(2, M/128), 256, GSMEM>>>(xn, wbuf+WO_QKV,  qkv_b,  nullptr, nullptr, q,  M, 256, 256, qscale, 0, 1);
    gemm_h<<<dim3(4, M/128), 256, GSMEM>>>(yn, wbuf+WO_QKV2, qkv2_b, qkv3_b,  nullptr, kv, M, 512, 256, 1.f, 0, 1);

    attn_kernel<<<dim3(2048, NHEAD/2), 256>>>(q, kv, rpb, ao);

    gemm_h<<<dim3(2, M/128), 256, GSMEM>>>(ao, wbuf+WO_PROJ, proj_b, nullptr, nullptr, po, M, 256, 256, 1.f, 0, 1);

    res_ln2_kernel<<<M/8, 256>>>(po, shrt, ln2_g, ln2_b, zt, ln2h);

    gemm_h<<<dim3(8, M/128), 256, GSMEM>>>(ln2h, wbuf+WO_FC1, fc1_b, nullptr, nullptr, hbuf, M, HID, 256, 1.f, 1, 1);
    gemm_h<<<dim3(2, M/128), 256, GSMEM>>>(hbuf, wbuf+WO_FC2, fc2_b, nullptr, zt,      out,  M, 256, HID, 1.f, 0, 2);
}